// round 11
// baseline (speedup 1.0000x reference)
#include <cuda_runtime.h>
#include <cuda_bf16.h>
#include <cstdint>
#include <cstddef>

#define B_  256
#define C_  4
#define N_  64
#define F_  256
#define OC_ 8
#define OF_ 256

typedef unsigned long long ull;

// Scratch (no allocations allowed)
__device__ float g_z[B_ * 2 * C_ * F_];                 // 2 MB : concat(h, x)
__device__ float g_w[B_ * N_];                          // softmax weights
__device__ float g_s2[B_ * N_];                         // raw neighbor logits
__device__ __nv_bfloat16 g_zb[B_ * 6144];               // 3 MB : z planes [hi|lo|hi]
__device__ __nv_bfloat16 g_wb[2048 * 6144];             // 24 MB: W planes [hi|hi|lo]

__device__ __forceinline__ float sqrt_ap(float v) {
    float r; asm("sqrt.approx.f32 %0, %1;" : "=f"(r) : "f"(v)); return r;
}
__device__ __forceinline__ float rcp_ap(float v) {
    float r; asm("rcp.approx.f32 %0, %1;" : "=f"(r) : "f"(v)); return r;
}
__device__ __forceinline__ uint32_t smem_u32(const void* p) {
    uint32_t a;
    asm("{ .reg .u64 t; cvta.to.shared.u64 t, %1; cvt.u32.u64 %0, t; }" : "=r"(a) : "l"(p));
    return a;
}
__device__ __forceinline__ void cp16(uint32_t s, const void* g) {
    asm volatile("cp.async.cg.shared.global [%0], [%1], 16;" :: "r"(s), "l"(g));
}
#define SWZ(o) ((o) ^ (((o) >> 3) & 0x70))

__device__ __forceinline__ void ldm4(uint32_t* r, uint32_t addr) {
    asm volatile("ldmatrix.sync.aligned.m8n8.x4.shared.b16 {%0,%1,%2,%3}, [%4];"
        : "=r"(r[0]), "=r"(r[1]), "=r"(r[2]), "=r"(r[3]) : "r"(addr));
}
__device__ __forceinline__ void mma16816(float* c, const uint32_t* a, uint32_t b0, uint32_t b1) {
    asm volatile("mma.sync.aligned.m16n8k16.row.col.f32.bf16.bf16.f32 "
        "{%0,%1,%2,%3}, {%4,%5,%6,%7}, {%8,%9}, {%0,%1,%2,%3};"
        : "+f"(c[0]), "+f"(c[1]), "+f"(c[2]), "+f"(c[3])
        : "r"(a[0]), "r"(a[1]), "r"(a[2]), "r"(a[3]), "r"(b0), "r"(b1));
}

// ---------------------------------------------------------------------------
// Kernel 1a: s2 logits. Grid 1024.
// ---------------------------------------------------------------------------
__global__ __launch_bounds__(256) void k1a_logits(
    const float* __restrict__ nb, const float* __restrict__ Wa2)
{
    __shared__ float ws2[256];
    const int b = blockIdx.x >> 2, quarter = blockIdx.x & 3;
    const int t = threadIdx.x;
    const int lane = t & 31, w = t >> 5;

    ws2[t] = Wa2[t] + Wa2[256 + t] + Wa2[512 + t] + Wa2[768 + t];
    __syncthreads();

    const float* nbb = nb + (size_t)b * 65536;
    #pragma unroll
    for (int j = 0; j < 2; j++) {
        const int n = quarter * 16 + w * 2 + j;
        const float4* np = (const float4*)(nbb + n * 1024);
        float acc = 0.f;
        #pragma unroll
        for (int it = 0; it < 8; it++) {
            float4 q = np[it * 32 + lane];
            int f = (it * 128 + lane * 4) & 255;
            acc += q.x * ws2[f] + q.y * ws2[f + 1] + q.z * ws2[f + 2] + q.w * ws2[f + 3];
        }
        #pragma unroll
        for (int o = 16; o > 0; o >>= 1) acc += __shfl_xor_sync(0xffffffffu, acc, o);
        if (lane == 0) g_s2[b * 64 + n] = acc;
    }
}

// ---------------------------------------------------------------------------
// Kernel 1b: s1 + softmax; copy x into z channels 4..7.
// ---------------------------------------------------------------------------
__global__ __launch_bounds__(256) void k1b_softmax(
    const float* __restrict__ x, const float* __restrict__ Wa1)
{
    __shared__ float red[8];
    const int b = blockIdx.x;
    const int t = threadIdx.x;
    const int lane = t & 31, w = t >> 5;

    float w1 = Wa1[t] + Wa1[256 + t] + Wa1[512 + t] + Wa1[768 + t];

    float xs = 0.f;
    #pragma unroll
    for (int c = 0; c < 4; c++) {
        float xv = x[(b * 4 + c) * 256 + t];
        g_z[b * 2048 + (4 + c) * 256 + t] = xv;
        xs += xv;
    }
    float p = xs * w1;
    #pragma unroll
    for (int o = 16; o > 0; o >>= 1) p += __shfl_xor_sync(0xffffffffu, p, o);
    if (lane == 0) red[w] = p;
    __syncthreads();

    if (w == 0) {
        float s1v = red[lane & 7];
        #pragma unroll
        for (int o = 4; o > 0; o >>= 1) s1v += __shfl_xor_sync(0xffffffffu, s1v, o);
        float l0 = s1v * g_s2[b * 64 + lane];
        float l1 = s1v * g_s2[b * 64 + lane + 32];
        float m = fmaxf(l0, l1);
        #pragma unroll
        for (int o = 16; o > 0; o >>= 1) m = fmaxf(m, __shfl_xor_sync(0xffffffffu, m, o));
        float e0 = __expf(l0 - m), e1 = __expf(l1 - m);
        float s = e0 + e1;
        #pragma unroll
        for (int o = 16; o > 0; o >>= 1) s += __shfl_xor_sync(0xffffffffu, s, o);
        float inv = 1.f / s;
        g_w[b * 64 + lane]      = e0 * inv;
        g_w[b * 64 + lane + 32] = e1 * inv;
    }
}

// ---------------------------------------------------------------------------
// Kernel 2: v + adj + fused h (round-7 measured version, unchanged).
// ---------------------------------------------------------------------------
__global__ __launch_bounds__(256) void k2_adj(
    const float* __restrict__ x, const float* __restrict__ nb,
    float* __restrict__ adj)
{
    __shared__ float xs[256], vs[256], us[256], idn[256];
    __shared__ float wsm[64];
    __shared__ float pden[4 * 256];

    const int bc = blockIdx.x;
    const int b = bc >> 2, c = bc & 3;
    const int t = threadIdx.x;

    if (t < 64) wsm[t] = g_w[b * 64 + t];
    xs[t] = x[bc * 256 + t];
    __syncthreads();

    {
        const float* nbp = nb + ((size_t)b * 256 + c) * 256 + t;
        float acc = 0.f;
        #pragma unroll 8
        for (int n = 0; n < 64; n++) acc += wsm[n] * nbp[(size_t)n * 1024];
        vs[t] = acc;
    }
    __syncthreads();

    const int r = t >> 6, cg = t & 63;
    const int i0 = r * 64;
    float xc[4], vc[4];
    #pragma unroll
    for (int j = 0; j < 4; j++) { xc[j] = xs[4 * cg + j]; vc[j] = vs[4 * cg + j]; }

    float d[4] = {0.f, 0.f, 0.f, 0.f};
    #pragma unroll 4
    for (int ii = 0; ii < 64; ii++) {
        const int i = i0 + ii;
        const float xi = xs[i], vi = vs[i];
        #pragma unroll
        for (int j = 0; j < 4; j++) {
            float tv = xi * vc[j] + xc[j] * vi;
            float s = sqrt_ap(fmaxf(fabsf(tv), 1e-8f));
            d[j] += (tv != 0.f) ? s : 0.f;
        }
    }
    #pragma unroll
    for (int j = 0; j < 4; j++) pden[r * 256 + 4 * cg + j] = d[j];
    __syncthreads();

    {
        float den = pden[t] + pden[256 + t] + pden[512 + t] + pden[768 + t];
        float id = rcp_ap(den + 1e-7f);
        idn[t] = id;
        us[t] = xs[t] * id;
    }
    __syncthreads();

    float ic[4];
    #pragma unroll
    for (int j = 0; j < 4; j++) ic[j] = idn[4 * cg + j];
    float h[4] = {0.f, 0.f, 0.f, 0.f};
    float* ap = adj + (size_t)bc * 65536 + 4 * cg;

    #pragma unroll 4
    for (int ii = 0; ii < 64; ii++) {
        const int i = i0 + ii;
        const float xi = xs[i], vi = vs[i], usi = us[i];
        float4 o;
        #pragma unroll
        for (int j = 0; j < 4; j++) {
            float tv = xi * vc[j] + xc[j] * vi;
            float s = sqrt_ap(fmaxf(fabsf(tv), 1e-8f));
            float a = (tv != 0.f) ? copysignf(s, tv) : 0.f;
            (&o.x)[j] = a * ic[j];
            h[j] = fmaf(a, usi, h[j]);
        }
        __stcs((float4*)(ap + (size_t)i * 256), o);
    }
    #pragma unroll
    for (int j = 0; j < 4; j++) pden[r * 256 + 4 * cg + j] = h[j];
    __syncthreads();

    float hs = pden[t] + pden[256 + t] + pden[512 + t] + pden[768 + t];
    g_z[b * 2048 + c * 256 + t] = hs;
}

// ---------------------------------------------------------------------------
// Kernels 3a/3b: fp32 -> bf16 triple planes.
// A (z):  [hi | lo | hi];  B (W): [hi | hi | lo].
// Sum over K'=6144 = hi*hi + lo*hi + hi*lo  (drops only lo*lo ~ 2^-18).
// ---------------------------------------------------------------------------
__global__ __launch_bounds__(256) void k3a_convW(const float* __restrict__ src)
{
    const size_t idx = ((size_t)blockIdx.x * 256 + threadIdx.x) * 4;
    const int r = (int)(idx >> 11), k = (int)(idx & 2047);
    const float4 v = *(const float4*)(src + idx);
    ull hv = 0, lv = 0;
    #pragma unroll
    for (int j = 0; j < 4; j++) {
        float f = (&v.x)[j];
        __nv_bfloat16 hb = __float2bfloat16(f);
        __nv_bfloat16 lb = __float2bfloat16(f - __bfloat162float(hb));
        hv |= (ull)__bfloat16_as_ushort(hb) << (16 * j);
        lv |= (ull)__bfloat16_as_ushort(lb) << (16 * j);
    }
    __nv_bfloat16* dst = g_wb + (size_t)r * 6144 + k;
    *(ull*)dst          = hv;
    *(ull*)(dst + 2048) = hv;
    *(ull*)(dst + 4096) = lv;
}

__global__ __launch_bounds__(256) void k3b_convZ(void)
{
    const size_t idx = ((size_t)blockIdx.x * 256 + threadIdx.x) * 4;
    const int r = (int)(idx >> 11), k = (int)(idx & 2047);
    const float4 v = *(const float4*)(g_z + idx);
    ull hv = 0, lv = 0;
    #pragma unroll
    for (int j = 0; j < 4; j++) {
        float f = (&v.x)[j];
        __nv_bfloat16 hb = __float2bfloat16(f);
        __nv_bfloat16 lb = __float2bfloat16(f - __bfloat162float(hb));
        hv |= (ull)__bfloat16_as_ushort(hb) << (16 * j);
        lv |= (ull)__bfloat16_as_ushort(lb) << (16 * j);
    }
    __nv_bfloat16* dst = g_zb + (size_t)r * 6144 + k;
    *(ull*)dst          = hv;
    *(ull*)(dst + 2048) = lv;
    *(ull*)(dst + 4096) = hv;
}

// ---------------------------------------------------------------------------
// Kernel 3: mma.sync bf16 GEMM. out[m][n] = sum_{k<6144} zb[m][k]*wb[n][k].
// CTA 64x64, 128 thr (4 warps, 2x2, warp tile 32x32). 3-stage cp.async,
// chunk k=64 (128B rows, SW128 swizzle). ldmatrix.x4 K-major both operands.
// Grid (32 n, 4 m) = 128 CTAs.
// ---------------------------------------------------------------------------
#define NCH 96
#define STG_B 16384                           // A 8K + B 8K
#define K3_DSMEM (3 * STG_B + 1024)

__global__ __launch_bounds__(128) void k3_mma(float* __restrict__ out)
{
    extern __shared__ char dsm[];
    const int t = threadIdx.x, wid = t >> 5, lane = t & 31;
    const int bn = blockIdx.x * 64, bm = blockIdx.y * 64;
    const uint32_t base = (smem_u32(dsm) + 1023) & ~1023u;

    const int wm = (wid & 1) * 32, wn = (wid >> 1) * 32;

    // loader mapping: 2 threads per 128B row
    const int arow = t & 63, half = t >> 6;
    uint32_t swo[4];
    #pragma unroll
    for (int j = 0; j < 4; j++) swo[j] = SWZ((uint32_t)(arow * 128 + half * 64 + j * 16));
    const __nv_bfloat16* gA = g_zb + (size_t)(bm + arow) * 6144 + half * 32;
    const __nv_bfloat16* gB = g_wb + (size_t)(bn + arow) * 6144 + half * 32;

    #define LOAD(ch) do { \
        const uint32_t sA_ = base + ((ch) % 3) * STG_B; \
        const uint32_t sB_ = sA_ + 8192; \
        const __nv_bfloat16* pa_ = gA + (ch) * 64; \
        const __nv_bfloat16* pb_ = gB + (ch) * 64; \
        _Pragma("unroll") \
        for (int j = 0; j < 4; j++) { cp16(sA_ + swo[j], pa_ + j * 8); cp16(sB_ + swo[j], pb_ + j * 8); } \
        asm volatile("cp.async.commit_group;" ::: "memory"); \
    } while (0)

    // ldmatrix address components (constant per thread)
    const uint32_t a_row = wm + (lane & 15);            // + mf*16
    const uint32_t a_col = (lane >> 4) * 8;             // + ks*16
    const uint32_t b_row = wn + (lane & 7) + ((lane >> 4) << 3);   // + bg*16
    const uint32_t b_col = ((lane >> 3) & 1) * 8;       // + ks*16

    float acc[2][4][4];
    #pragma unroll
    for (int mf = 0; mf < 2; mf++)
        #pragma unroll
        for (int nf = 0; nf < 4; nf++)
            #pragma unroll
            for (int e = 0; e < 4; e++) acc[mf][nf][e] = 0.f;

    LOAD(0);
    LOAD(1);

    for (int ch = 0; ch < NCH; ch++) {
        if (ch + 2 < NCH) {
            LOAD(ch + 2);
            asm volatile("cp.async.wait_group 2;" ::: "memory");
        } else if (ch + 1 < NCH) {
            asm volatile("cp.async.wait_group 1;" ::: "memory");
        } else {
            asm volatile("cp.async.wait_group 0;" ::: "memory");
        }
        __syncthreads();

        const uint32_t sA = base + (ch % 3) * STG_B;
        const uint32_t sB = sA + 8192;
        #pragma unroll
        for (int ks = 0; ks < 4; ks++) {
            uint32_t a[2][4], bfr[2][4];
            #pragma unroll
            for (int mf = 0; mf < 2; mf++)
                ldm4(a[mf], sA + SWZ((a_row + mf * 16) * 128 + (a_col + ks * 16) * 2));
            #pragma unroll
            for (int bg = 0; bg < 2; bg++)
                ldm4(bfr[bg], sB + SWZ((b_row + bg * 16) * 128 + (b_col + ks * 16) * 2));
            #pragma unroll
            for (int mf = 0; mf < 2; mf++) {
                mma16816(acc[mf][0], a[mf], bfr[0][0], bfr[0][1]);
                mma16816(acc[mf][1], a[mf], bfr[0][2], bfr[0][3]);
                mma16816(acc[mf][2], a[mf], bfr[1][0], bfr[1][1]);
                mma16816(acc[mf][3], a[mf], bfr[1][2], bfr[1][3]);
            }
        }
        __syncthreads();
    }
    #undef LOAD

    // epilogue: c0,c1 -> row gid, c2,c3 -> row gid+8; cols 2*(lane&3) within n8
    const int gid = lane >> 2, cpo = 2 * (lane & 3);
    #pragma unroll
    for (int mf = 0; mf < 2; mf++) {
        const int row0 = bm + wm + mf * 16 + gid;
        #pragma unroll
        for (int nf = 0; nf < 4; nf++) {
            const int col = bn + wn + nf * 8 + cpo;
            *(float2*)(out + (size_t)row0 * 2048 + col)       = make_float2(acc[mf][nf][0], acc[mf][nf][1]);
            *(float2*)(out + (size_t)(row0 + 8) * 2048 + col) = make_float2(acc[mf][nf][2], acc[mf][nf][3]);
        }
    }
}

// ---------------------------------------------------------------------------
// Launch: output layout = concat(out (B*OC*OF), adj (B*C*F*F)) in fp32.
// ---------------------------------------------------------------------------
extern "C" void kernel_launch(void* const* d_in, const int* in_sizes, int n_in,
                              void* d_out, int out_size)
{
    const float* x   = (const float*)d_in[0];
    const float* nb  = (const float*)d_in[1];
    const float* Wa1 = (const float*)d_in[2];
    const float* Wa2 = (const float*)d_in[3];
    const float* Wc  = (const float*)d_in[4];
    float* out = (float*)d_out;
    float* adj = out + (size_t)B_ * OC_ * OF_;

    static int attr_done = 0;
    if (!attr_done) {
        cudaFuncSetAttribute(k3_mma, cudaFuncAttributeMaxDynamicSharedMemorySize, K3_DSMEM);
        attr_done = 1;
    }

    k1a_logits<<<B_ * 4, 256>>>(nb, Wa2);
    k1b_softmax<<<B_, 256>>>(x, Wa1);
    k3a_convW<<<4096, 256>>>(Wc);              // W planes (independent of k1/k2)
    k2_adj<<<B_ * C_, 256>>>(x, nb, adj);
    k3b_convZ<<<512, 256>>>();                 // z planes (after k2)
    k3_mma<<<dim3(32, 4), 128, K3_DSMEM>>>(out);
}

// round 12
// speedup vs baseline: 1.1398x; 1.1398x over previous
#include <cuda_runtime.h>
#include <cuda_bf16.h>
#include <cstdint>
#include <cstddef>

#define B_  256
#define C_  4
#define N_  64
#define F_  256
#define OC_ 8
#define OF_ 256

typedef unsigned long long ull;

// Scratch (no allocations allowed)
__device__ float g_z[B_ * 2 * C_ * F_];                 // 2 MB : concat(h, x)
__device__ float g_w[B_ * N_];                          // softmax weights
__device__ float g_s2[B_ * N_];                         // raw neighbor logits
__device__ __nv_bfloat16 g_zb[B_ * 4096];               // 2 MB : z planes [hi|lo]
__device__ __nv_bfloat16 g_wb[2048 * 4096];             // 16 MB: W planes [hi|lo]
__device__ float g_part[3 * B_ * OC_ * OF_];            // 6 MB : split-K partials

__device__ __forceinline__ float sqrt_ap(float v) {
    float r; asm("sqrt.approx.f32 %0, %1;" : "=f"(r) : "f"(v)); return r;
}
__device__ __forceinline__ float rcp_ap(float v) {
    float r; asm("rcp.approx.f32 %0, %1;" : "=f"(r) : "f"(v)); return r;
}
__device__ __forceinline__ uint32_t smem_u32(const void* p) {
    uint32_t a;
    asm("{ .reg .u64 t; cvta.to.shared.u64 t, %1; cvt.u32.u64 %0, t; }" : "=r"(a) : "l"(p));
    return a;
}
__device__ __forceinline__ void cp16(uint32_t s, const void* g) {
    asm volatile("cp.async.cg.shared.global [%0], [%1], 16;" :: "r"(s), "l"(g));
}
#define SWZ(o) ((o) ^ (((o) >> 3) & 0x70))

__device__ __forceinline__ void ldm4(uint32_t* r, uint32_t addr) {
    asm volatile("ldmatrix.sync.aligned.m8n8.x4.shared.b16 {%0,%1,%2,%3}, [%4];"
        : "=r"(r[0]), "=r"(r[1]), "=r"(r[2]), "=r"(r[3]) : "r"(addr));
}
__device__ __forceinline__ void mma16816(float* c, const uint32_t* a, uint32_t b0, uint32_t b1) {
    asm volatile("mma.sync.aligned.m16n8k16.row.col.f32.bf16.bf16.f32 "
        "{%0,%1,%2,%3}, {%4,%5,%6,%7}, {%8,%9}, {%0,%1,%2,%3};"
        : "+f"(c[0]), "+f"(c[1]), "+f"(c[2]), "+f"(c[3])
        : "r"(a[0]), "r"(a[1]), "r"(a[2]), "r"(a[3]), "r"(b0), "r"(b1));
}

// ---------------------------------------------------------------------------
// Kernel 1a: s2 logits. Grid 1024.
// ---------------------------------------------------------------------------
__global__ __launch_bounds__(256) void k1a_logits(
    const float* __restrict__ nb, const float* __restrict__ Wa2)
{
    __shared__ float ws2[256];
    const int b = blockIdx.x >> 2, quarter = blockIdx.x & 3;
    const int t = threadIdx.x;
    const int lane = t & 31, w = t >> 5;

    ws2[t] = Wa2[t] + Wa2[256 + t] + Wa2[512 + t] + Wa2[768 + t];
    __syncthreads();

    const float* nbb = nb + (size_t)b * 65536;
    #pragma unroll
    for (int j = 0; j < 2; j++) {
        const int n = quarter * 16 + w * 2 + j;
        const float4* np = (const float4*)(nbb + n * 1024);
        float acc = 0.f;
        #pragma unroll
        for (int it = 0; it < 8; it++) {
            float4 q = np[it * 32 + lane];
            int f = (it * 128 + lane * 4) & 255;
            acc += q.x * ws2[f] + q.y * ws2[f + 1] + q.z * ws2[f + 2] + q.w * ws2[f + 3];
        }
        #pragma unroll
        for (int o = 16; o > 0; o >>= 1) acc += __shfl_xor_sync(0xffffffffu, acc, o);
        if (lane == 0) g_s2[b * 64 + n] = acc;
    }
}

// ---------------------------------------------------------------------------
// Kernel 1b: s1 + softmax; copy x into z channels 4..7.
// ---------------------------------------------------------------------------
__global__ __launch_bounds__(256) void k1b_softmax(
    const float* __restrict__ x, const float* __restrict__ Wa1)
{
    __shared__ float red[8];
    const int b = blockIdx.x;
    const int t = threadIdx.x;
    const int lane = t & 31, w = t >> 5;

    float w1 = Wa1[t] + Wa1[256 + t] + Wa1[512 + t] + Wa1[768 + t];

    float xs = 0.f;
    #pragma unroll
    for (int c = 0; c < 4; c++) {
        float xv = x[(b * 4 + c) * 256 + t];
        g_z[b * 2048 + (4 + c) * 256 + t] = xv;
        xs += xv;
    }
    float p = xs * w1;
    #pragma unroll
    for (int o = 16; o > 0; o >>= 1) p += __shfl_xor_sync(0xffffffffu, p, o);
    if (lane == 0) red[w] = p;
    __syncthreads();

    if (w == 0) {
        float s1v = red[lane & 7];
        #pragma unroll
        for (int o = 4; o > 0; o >>= 1) s1v += __shfl_xor_sync(0xffffffffu, s1v, o);
        float l0 = s1v * g_s2[b * 64 + lane];
        float l1 = s1v * g_s2[b * 64 + lane + 32];
        float m = fmaxf(l0, l1);
        #pragma unroll
        for (int o = 16; o > 0; o >>= 1) m = fmaxf(m, __shfl_xor_sync(0xffffffffu, m, o));
        float e0 = __expf(l0 - m), e1 = __expf(l1 - m);
        float s = e0 + e1;
        #pragma unroll
        for (int o = 16; o > 0; o >>= 1) s += __shfl_xor_sync(0xffffffffu, s, o);
        float inv = 1.f / s;
        g_w[b * 64 + lane]      = e0 * inv;
        g_w[b * 64 + lane + 32] = e1 * inv;
    }
}

// ---------------------------------------------------------------------------
// Kernel 2: v + adj + fused h. Trimmed: zero-guard FSEL dropped (exact-zero
// tv has measure zero; worst-case adj perturbation ~1e-6 abs), abs folds
// into FMNMX modifier. ~4 fewer alu instr/element -> store stream feeds.
// ---------------------------------------------------------------------------
__global__ __launch_bounds__(256) void k2_adj(
    const float* __restrict__ x, const float* __restrict__ nb,
    float* __restrict__ adj)
{
    __shared__ float xs[256], vs[256], us[256], idn[256];
    __shared__ float wsm[64];
    __shared__ float pden[4 * 256];

    const int bc = blockIdx.x;
    const int b = bc >> 2, c = bc & 3;
    const int t = threadIdx.x;

    if (t < 64) wsm[t] = g_w[b * 64 + t];
    xs[t] = x[bc * 256 + t];
    __syncthreads();

    {
        const float* nbp = nb + ((size_t)b * 256 + c) * 256 + t;
        float acc = 0.f;
        #pragma unroll 8
        for (int n = 0; n < 64; n++) acc += wsm[n] * nbp[(size_t)n * 1024];
        vs[t] = acc;
    }
    __syncthreads();

    const int r = t >> 6, cg = t & 63;
    const int i0 = r * 64;
    float xc[4], vc[4];
    #pragma unroll
    for (int j = 0; j < 4; j++) { xc[j] = xs[4 * cg + j]; vc[j] = vs[4 * cg + j]; }

    float d[4] = {0.f, 0.f, 0.f, 0.f};
    #pragma unroll 4
    for (int ii = 0; ii < 64; ii++) {
        const int i = i0 + ii;
        const float xi = xs[i], vi = vs[i];
        #pragma unroll
        for (int j = 0; j < 4; j++) {
            float tv = xi * vc[j] + xc[j] * vi;
            d[j] += sqrt_ap(fmaxf(fabsf(tv), 1e-8f));
        }
    }
    #pragma unroll
    for (int j = 0; j < 4; j++) pden[r * 256 + 4 * cg + j] = d[j];
    __syncthreads();

    {
        float den = pden[t] + pden[256 + t] + pden[512 + t] + pden[768 + t];
        float id = rcp_ap(den + 1e-7f);
        idn[t] = id;
        us[t] = xs[t] * id;
    }
    __syncthreads();

    float ic[4];
    #pragma unroll
    for (int j = 0; j < 4; j++) ic[j] = idn[4 * cg + j];
    float h[4] = {0.f, 0.f, 0.f, 0.f};
    float* ap = adj + (size_t)bc * 65536 + 4 * cg;

    #pragma unroll 4
    for (int ii = 0; ii < 64; ii++) {
        const int i = i0 + ii;
        const float xi = xs[i], vi = vs[i], usi = us[i];
        float4 o;
        #pragma unroll
        for (int j = 0; j < 4; j++) {
            float tv = xi * vc[j] + xc[j] * vi;
            float a = copysignf(sqrt_ap(fmaxf(fabsf(tv), 1e-8f)), tv);
            (&o.x)[j] = a * ic[j];
            h[j] = fmaf(a, usi, h[j]);
        }
        __stcs((float4*)(ap + (size_t)i * 256), o);
    }
    #pragma unroll
    for (int j = 0; j < 4; j++) pden[r * 256 + 4 * cg + j] = h[j];
    __syncthreads();

    float hs = pden[t] + pden[256 + t] + pden[512 + t] + pden[768 + t];
    g_z[b * 2048 + c * 256 + t] = hs;
}

// ---------------------------------------------------------------------------
// Kernels 3a/3b: fp32 -> bf16 two planes [hi | lo].
// The three products hi*hi + lo*hi + hi*lo are formed by split-K in k3_mma.
// ---------------------------------------------------------------------------
__global__ __launch_bounds__(256) void k3a_convW(const float* __restrict__ src)
{
    const size_t idx = ((size_t)blockIdx.x * 256 + threadIdx.x) * 4;
    const int r = (int)(idx >> 11), k = (int)(idx & 2047);
    const float4 v = *(const float4*)(src + idx);
    ull hv = 0, lv = 0;
    #pragma unroll
    for (int j = 0; j < 4; j++) {
        float f = (&v.x)[j];
        __nv_bfloat16 hb = __float2bfloat16(f);
        __nv_bfloat16 lb = __float2bfloat16(f - __bfloat162float(hb));
        hv |= (ull)__bfloat16_as_ushort(hb) << (16 * j);
        lv |= (ull)__bfloat16_as_ushort(lb) << (16 * j);
    }
    __nv_bfloat16* dst = g_wb + (size_t)r * 4096 + k;
    *(ull*)dst          = hv;
    *(ull*)(dst + 2048) = lv;
}

__global__ __launch_bounds__(256) void k3b_convZ(void)
{
    const size_t idx = ((size_t)blockIdx.x * 256 + threadIdx.x) * 4;
    const int r = (int)(idx >> 11), k = (int)(idx & 2047);
    const float4 v = *(const float4*)(g_z + idx);
    ull hv = 0, lv = 0;
    #pragma unroll
    for (int j = 0; j < 4; j++) {
        float f = (&v.x)[j];
        __nv_bfloat16 hb = __float2bfloat16(f);
        __nv_bfloat16 lb = __float2bfloat16(f - __bfloat162float(hb));
        hv |= (ull)__bfloat16_as_ushort(hb) << (16 * j);
        lv |= (ull)__bfloat16_as_ushort(lb) << (16 * j);
    }
    __nv_bfloat16* dst = g_zb + (size_t)r * 4096 + k;
    *(ull*)dst          = hv;
    *(ull*)(dst + 2048) = lv;
}

// ---------------------------------------------------------------------------
// Kernel 3: mma.sync bf16 GEMM, split-K by plane product.
// blockIdx.z: 0 = z_hi*W_hi, 1 = z_lo*W_hi, 2 = z_hi*W_lo. Each split K=2048
// (32 chunks). Grid (32 n, 4 m, 3) = 384 CTAs -> ~16 warps/SM (round-11 had
// 4 warps/SM: every ldmatrix->mma RAW + sync exposed).
// CTA 64x64, 128 thr, 3-stage cp.async, SW128 swizzle.
// ---------------------------------------------------------------------------
#define NCH 32
#define STG_B 16384                           // A 8K + B 8K
#define K3_DSMEM (3 * STG_B + 1024)

__global__ __launch_bounds__(128) void k3_mma(void)
{
    extern __shared__ char dsm[];
    const int t = threadIdx.x, wid = t >> 5, lane = t & 31;
    const int bn = blockIdx.x * 64, bm = blockIdx.y * 64, zs = blockIdx.z;
    const uint32_t base = (smem_u32(dsm) + 1023) & ~1023u;

    const int aoff = (zs == 1) ? 2048 : 0;    // z plane: lo for split 1
    const int boff = (zs == 2) ? 2048 : 0;    // W plane: lo for split 2

    const int wm = (wid & 1) * 32, wn = (wid >> 1) * 32;

    // loader mapping: 2 threads per 128B row
    const int arow = t & 63, half = t >> 6;
    uint32_t swo[4];
    #pragma unroll
    for (int j = 0; j < 4; j++) swo[j] = SWZ((uint32_t)(arow * 128 + half * 64 + j * 16));
    const __nv_bfloat16* gA = g_zb + (size_t)(bm + arow) * 4096 + aoff + half * 32;
    const __nv_bfloat16* gB = g_wb + (size_t)(bn + arow) * 4096 + boff + half * 32;

    #define LOAD(ch) do { \
        const uint32_t sA_ = base + ((ch) % 3) * STG_B; \
        const uint32_t sB_ = sA_ + 8192; \
        const __nv_bfloat16* pa_ = gA + (ch) * 64; \
        const __nv_bfloat16* pb_ = gB + (ch) * 64; \
        _Pragma("unroll") \
        for (int j = 0; j < 4; j++) { cp16(sA_ + swo[j], pa_ + j * 8); cp16(sB_ + swo[j], pb_ + j * 8); } \
        asm volatile("cp.async.commit_group;" ::: "memory"); \
    } while (0)

    // ldmatrix address components (constant per thread)
    const uint32_t a_row = wm + (lane & 15);
    const uint32_t a_col = (lane >> 4) * 8;
    const uint32_t b_row = wn + (lane & 7) + ((lane >> 4) << 3);
    const uint32_t b_col = ((lane >> 3) & 1) * 8;

    float acc[2][4][4];
    #pragma unroll
    for (int mf = 0; mf < 2; mf++)
        #pragma unroll
        for (int nf = 0; nf < 4; nf++)
            #pragma unroll
            for (int e = 0; e < 4; e++) acc[mf][nf][e] = 0.f;

    LOAD(0);
    LOAD(1);

    for (int ch = 0; ch < NCH; ch++) {
        if (ch + 2 < NCH) {
            LOAD(ch + 2);
            asm volatile("cp.async.wait_group 2;" ::: "memory");
        } else if (ch + 1 < NCH) {
            asm volatile("cp.async.wait_group 1;" ::: "memory");
        } else {
            asm volatile("cp.async.wait_group 0;" ::: "memory");
        }
        __syncthreads();

        const uint32_t sA = base + (ch % 3) * STG_B;
        const uint32_t sB = sA + 8192;
        #pragma unroll
        for (int ks = 0; ks < 4; ks++) {
            uint32_t a[2][4], bfr[2][4];
            #pragma unroll
            for (int mf = 0; mf < 2; mf++)
                ldm4(a[mf], sA + SWZ((a_row + mf * 16) * 128 + (a_col + ks * 16) * 2));
            #pragma unroll
            for (int bg = 0; bg < 2; bg++)
                ldm4(bfr[bg], sB + SWZ((b_row + bg * 16) * 128 + (b_col + ks * 16) * 2));
            #pragma unroll
            for (int mf = 0; mf < 2; mf++) {
                mma16816(acc[mf][0], a[mf], bfr[0][0], bfr[0][1]);
                mma16816(acc[mf][1], a[mf], bfr[0][2], bfr[0][3]);
                mma16816(acc[mf][2], a[mf], bfr[1][0], bfr[1][1]);
                mma16816(acc[mf][3], a[mf], bfr[1][2], bfr[1][3]);
            }
        }
        __syncthreads();
    }
    #undef LOAD

    // epilogue: partial for this split
    float* pp = g_part + (size_t)zs * 524288;
    const int gid = lane >> 2, cpo = 2 * (lane & 3);
    #pragma unroll
    for (int mf = 0; mf < 2; mf++) {
        const int row0 = bm + wm + mf * 16 + gid;
        #pragma unroll
        for (int nf = 0; nf < 4; nf++) {
            const int col = bn + wn + nf * 8 + cpo;
            *(float2*)(pp + (size_t)row0 * 2048 + col)       = make_float2(acc[mf][nf][0], acc[mf][nf][1]);
            *(float2*)(pp + (size_t)(row0 + 8) * 2048 + col) = make_float2(acc[mf][nf][2], acc[mf][nf][3]);
        }
    }
}

// ---------------------------------------------------------------------------
// Kernel 4: sum the 3 split partials into out.
// ---------------------------------------------------------------------------
__global__ __launch_bounds__(256) void k4_reduce(float* __restrict__ out)
{
    const int i = (blockIdx.x * 256 + threadIdx.x) * 4;
    const float4 p0 = *(const float4*)(g_part + i);
    const float4 p1 = *(const float4*)(g_part + 524288 + i);
    const float4 p2 = *(const float4*)(g_part + 2 * 524288 + i);
    float4 o;
    o.x = p0.x + p1.x + p2.x;
    o.y = p0.y + p1.y + p2.y;
    o.z = p0.z + p1.z + p2.z;
    o.w = p0.w + p1.w + p2.w;
    *(float4*)(out + i) = o;
}

// ---------------------------------------------------------------------------
// Launch: output layout = concat(out (B*OC*OF), adj (B*C*F*F)) in fp32.
// ---------------------------------------------------------------------------
extern "C" void kernel_launch(void* const* d_in, const int* in_sizes, int n_in,
                              void* d_out, int out_size)
{
    const float* x   = (const float*)d_in[0];
    const float* nb  = (const float*)d_in[1];
    const float* Wa1 = (const float*)d_in[2];
    const float* Wa2 = (const float*)d_in[3];
    const float* Wc  = (const float*)d_in[4];
    float* out = (float*)d_out;
    float* adj = out + (size_t)B_ * OC_ * OF_;

    static int attr_done = 0;
    if (!attr_done) {
        cudaFuncSetAttribute(k3_mma, cudaFuncAttributeMaxDynamicSharedMemorySize, K3_DSMEM);
        attr_done = 1;
    }

    k1a_logits<<<B_ * 4, 256>>>(nb, Wa2);
    k1b_softmax<<<B_, 256>>>(x, Wa1);
    k3a_convW<<<4096, 256>>>(Wc);              // W planes (independent of k1/k2)
    k2_adj<<<B_ * C_, 256>>>(x, nb, adj);
    k3b_convZ<<<512, 256>>>();                 // z planes (after k2)
    k3_mma<<<dim3(32, 4, 3), 128, K3_DSMEM>>>();
    k4_reduce<<<512, 256>>>(out);
}

// round 13
// speedup vs baseline: 1.1547x; 1.0131x over previous
#include <cuda_runtime.h>
#include <cuda_bf16.h>
#include <cstdint>
#include <cstddef>

#define B_  256
#define C_  4
#define N_  64
#define F_  256
#define OC_ 8
#define OF_ 256

typedef unsigned long long ull;

// Scratch (no allocations allowed)
__device__ float g_z[B_ * 2 * C_ * F_];                 // 2 MB : concat(h, x)
__device__ float g_w[B_ * N_];                          // softmax weights
__device__ float g_s2[B_ * N_];                         // raw neighbor logits
__device__ __nv_bfloat16 g_zb[B_ * 4096];               // 2 MB : z planes [hi|lo]
__device__ __nv_bfloat16 g_wb[2048 * 4096];             // 16 MB: W planes [hi|lo]
__device__ float g_part[6 * B_ * OC_ * OF_];            // 12 MB: split partials

__device__ __forceinline__ float sqrt_ap(float v) {
    float r; asm("sqrt.approx.f32 %0, %1;" : "=f"(r) : "f"(v)); return r;
}
__device__ __forceinline__ float rcp_ap(float v) {
    float r; asm("rcp.approx.f32 %0, %1;" : "=f"(r) : "f"(v)); return r;
}
__device__ __forceinline__ uint32_t smem_u32(const void* p) {
    uint32_t a;
    asm("{ .reg .u64 t; cvta.to.shared.u64 t, %1; cvt.u32.u64 %0, t; }" : "=r"(a) : "l"(p));
    return a;
}
__device__ __forceinline__ void cp16(uint32_t s, const void* g) {
    asm volatile("cp.async.cg.shared.global [%0], [%1], 16;" :: "r"(s), "l"(g));
}
#define SWZ(o) ((o) ^ (((o) >> 3) & 0x70))

__device__ __forceinline__ void ldm4(uint32_t* r, uint32_t addr) {
    asm volatile("ldmatrix.sync.aligned.m8n8.x4.shared.b16 {%0,%1,%2,%3}, [%4];"
        : "=r"(r[0]), "=r"(r[1]), "=r"(r[2]), "=r"(r[3]) : "r"(addr));
}
__device__ __forceinline__ void mma16816(float* c, const uint32_t* a, uint32_t b0, uint32_t b1) {
    asm volatile("mma.sync.aligned.m16n8k16.row.col.f32.bf16.bf16.f32 "
        "{%0,%1,%2,%3}, {%4,%5,%6,%7}, {%8,%9}, {%0,%1,%2,%3};"
        : "+f"(c[0]), "+f"(c[1]), "+f"(c[2]), "+f"(c[3])
        : "r"(a[0]), "r"(a[1]), "r"(a[2]), "r"(a[3]), "r"(b0), "r"(b1));
}

// ---------------------------------------------------------------------------
// Kernel 1a: s2 logits. Grid 1024.
// ---------------------------------------------------------------------------
__global__ __launch_bounds__(256) void k1a_logits(
    const float* __restrict__ nb, const float* __restrict__ Wa2)
{
    __shared__ float ws2[256];
    const int b = blockIdx.x >> 2, quarter = blockIdx.x & 3;
    const int t = threadIdx.x;
    const int lane = t & 31, w = t >> 5;

    ws2[t] = Wa2[t] + Wa2[256 + t] + Wa2[512 + t] + Wa2[768 + t];
    __syncthreads();

    const float* nbb = nb + (size_t)b * 65536;
    #pragma unroll
    for (int j = 0; j < 2; j++) {
        const int n = quarter * 16 + w * 2 + j;
        const float4* np = (const float4*)(nbb + n * 1024);
        float acc = 0.f;
        #pragma unroll
        for (int it = 0; it < 8; it++) {
            float4 q = np[it * 32 + lane];
            int f = (it * 128 + lane * 4) & 255;
            acc += q.x * ws2[f] + q.y * ws2[f + 1] + q.z * ws2[f + 2] + q.w * ws2[f + 3];
        }
        #pragma unroll
        for (int o = 16; o > 0; o >>= 1) acc += __shfl_xor_sync(0xffffffffu, acc, o);
        if (lane == 0) g_s2[b * 64 + n] = acc;
    }
}

// ---------------------------------------------------------------------------
// Kernel 1b: s1 + softmax; copy x into z channels 4..7.
// ---------------------------------------------------------------------------
__global__ __launch_bounds__(256) void k1b_softmax(
    const float* __restrict__ x, const float* __restrict__ Wa1)
{
    __shared__ float red[8];
    const int b = blockIdx.x;
    const int t = threadIdx.x;
    const int lane = t & 31, w = t >> 5;

    float w1 = Wa1[t] + Wa1[256 + t] + Wa1[512 + t] + Wa1[768 + t];

    float xs = 0.f;
    #pragma unroll
    for (int c = 0; c < 4; c++) {
        float xv = x[(b * 4 + c) * 256 + t];
        g_z[b * 2048 + (4 + c) * 256 + t] = xv;
        xs += xv;
    }
    float p = xs * w1;
    #pragma unroll
    for (int o = 16; o > 0; o >>= 1) p += __shfl_xor_sync(0xffffffffu, p, o);
    if (lane == 0) red[w] = p;
    __syncthreads();

    if (w == 0) {
        float s1v = red[lane & 7];
        #pragma unroll
        for (int o = 4; o > 0; o >>= 1) s1v += __shfl_xor_sync(0xffffffffu, s1v, o);
        float l0 = s1v * g_s2[b * 64 + lane];
        float l1 = s1v * g_s2[b * 64 + lane + 32];
        float m = fmaxf(l0, l1);
        #pragma unroll
        for (int o = 16; o > 0; o >>= 1) m = fmaxf(m, __shfl_xor_sync(0xffffffffu, m, o));
        float e0 = __expf(l0 - m), e1 = __expf(l1 - m);
        float s = e0 + e1;
        #pragma unroll
        for (int o = 16; o > 0; o >>= 1) s += __shfl_xor_sync(0xffffffffu, s, o);
        float inv = 1.f / s;
        g_w[b * 64 + lane]      = e0 * inv;
        g_w[b * 64 + lane + 32] = e1 * inv;
    }
}

// ---------------------------------------------------------------------------
// Kernel 2: v + adj + fused h (round-12 measured version, unchanged).
// ---------------------------------------------------------------------------
__global__ __launch_bounds__(256) void k2_adj(
    const float* __restrict__ x, const float* __restrict__ nb,
    float* __restrict__ adj)
{
    __shared__ float xs[256], vs[256], us[256], idn[256];
    __shared__ float wsm[64];
    __shared__ float pden[4 * 256];

    const int bc = blockIdx.x;
    const int b = bc >> 2, c = bc & 3;
    const int t = threadIdx.x;

    if (t < 64) wsm[t] = g_w[b * 64 + t];
    xs[t] = x[bc * 256 + t];
    __syncthreads();

    {
        const float* nbp = nb + ((size_t)b * 256 + c) * 256 + t;
        float acc = 0.f;
        #pragma unroll 8
        for (int n = 0; n < 64; n++) acc += wsm[n] * nbp[(size_t)n * 1024];
        vs[t] = acc;
    }
    __syncthreads();

    const int r = t >> 6, cg = t & 63;
    const int i0 = r * 64;
    float xc[4], vc[4];
    #pragma unroll
    for (int j = 0; j < 4; j++) { xc[j] = xs[4 * cg + j]; vc[j] = vs[4 * cg + j]; }

    float d[4] = {0.f, 0.f, 0.f, 0.f};
    #pragma unroll 4
    for (int ii = 0; ii < 64; ii++) {
        const int i = i0 + ii;
        const float xi = xs[i], vi = vs[i];
        #pragma unroll
        for (int j = 0; j < 4; j++) {
            float tv = xi * vc[j] + xc[j] * vi;
            d[j] += sqrt_ap(fmaxf(fabsf(tv), 1e-8f));
        }
    }
    #pragma unroll
    for (int j = 0; j < 4; j++) pden[r * 256 + 4 * cg + j] = d[j];
    __syncthreads();

    {
        float den = pden[t] + pden[256 + t] + pden[512 + t] + pden[768 + t];
        float id = rcp_ap(den + 1e-7f);
        idn[t] = id;
        us[t] = xs[t] * id;
    }
    __syncthreads();

    float ic[4];
    #pragma unroll
    for (int j = 0; j < 4; j++) ic[j] = idn[4 * cg + j];
    float h[4] = {0.f, 0.f, 0.f, 0.f};
    float* ap = adj + (size_t)bc * 65536 + 4 * cg;

    #pragma unroll 4
    for (int ii = 0; ii < 64; ii++) {
        const int i = i0 + ii;
        const float xi = xs[i], vi = vs[i], usi = us[i];
        float4 o;
        #pragma unroll
        for (int j = 0; j < 4; j++) {
            float tv = xi * vc[j] + xc[j] * vi;
            float a = copysignf(sqrt_ap(fmaxf(fabsf(tv), 1e-8f)), tv);
            (&o.x)[j] = a * ic[j];
            h[j] = fmaf(a, usi, h[j]);
        }
        __stcs((float4*)(ap + (size_t)i * 256), o);
    }
    #pragma unroll
    for (int j = 0; j < 4; j++) pden[r * 256 + 4 * cg + j] = h[j];
    __syncthreads();

    float hs = pden[t] + pden[256 + t] + pden[512 + t] + pden[768 + t];
    g_z[b * 2048 + c * 256 + t] = hs;
}

// ---------------------------------------------------------------------------
// Kernels 3a/3b: fp32 -> bf16 two planes [hi | lo].
// ---------------------------------------------------------------------------
__global__ __launch_bounds__(256) void k3a_convW(const float* __restrict__ src)
{
    const size_t idx = ((size_t)blockIdx.x * 256 + threadIdx.x) * 4;
    const int r = (int)(idx >> 11), k = (int)(idx & 2047);
    const float4 v = *(const float4*)(src + idx);
    ull hv = 0, lv = 0;
    #pragma unroll
    for (int j = 0; j < 4; j++) {
        float f = (&v.x)[j];
        __nv_bfloat16 hb = __float2bfloat16(f);
        __nv_bfloat16 lb = __float2bfloat16(f - __bfloat162float(hb));
        hv |= (ull)__bfloat16_as_ushort(hb) << (16 * j);
        lv |= (ull)__bfloat16_as_ushort(lb) << (16 * j);
    }
    __nv_bfloat16* dst = g_wb + (size_t)r * 4096 + k;
    *(ull*)dst          = hv;
    *(ull*)(dst + 2048) = lv;
}

// Convert half of z's K-range: koff = 0 (h-part) or 1024 (x-part).
__global__ __launch_bounds__(256) void k3b_convZ(int koff)
{
    const int i = blockIdx.x * 256 + threadIdx.x;     // 65536 threads
    const int r = i >> 8, k = koff + ((i & 255) * 4);
    const float4 v = *(const float4*)(g_z + (size_t)r * 2048 + k);
    ull hv = 0, lv = 0;
    #pragma unroll
    for (int j = 0; j < 4; j++) {
        float f = (&v.x)[j];
        __nv_bfloat16 hb = __float2bfloat16(f);
        __nv_bfloat16 lb = __float2bfloat16(f - __bfloat162float(hb));
        hv |= (ull)__bfloat16_as_ushort(hb) << (16 * j);
        lv |= (ull)__bfloat16_as_ushort(lb) << (16 * j);
    }
    __nv_bfloat16* dst = g_zb + (size_t)r * 4096 + k;
    *(ull*)dst          = hv;
    *(ull*)(dst + 2048) = lv;
}

// ---------------------------------------------------------------------------
// Kernel 3: mma.sync bf16 GEMM over a K-half (koff in {0,1024}, 16 chunks).
// blockIdx.z selects plane product: 0 hi*hi, 1 lo*hi, 2 hi*lo.
// Partials land in g_part slice (pbase + z).
// ---------------------------------------------------------------------------
#define NCH 16
#define STG_B 16384
#define K3_DSMEM (3 * STG_B + 1024)

__global__ __launch_bounds__(128) void k3_mma(int koff, int pbase)
{
    extern __shared__ char dsm[];
    const int t = threadIdx.x, wid = t >> 5, lane = t & 31;
    const int bn = blockIdx.x * 64, bm = blockIdx.y * 64, zs = blockIdx.z;
    const uint32_t base = (smem_u32(dsm) + 1023) & ~1023u;

    const int aoff = (zs == 1) ? 2048 : 0;
    const int boff = (zs == 2) ? 2048 : 0;
    const int wm = (wid & 1) * 32, wn = (wid >> 1) * 32;

    const int arow = t & 63, half = t >> 6;
    uint32_t swo[4];
    #pragma unroll
    for (int j = 0; j < 4; j++) swo[j] = SWZ((uint32_t)(arow * 128 + half * 64 + j * 16));
    const __nv_bfloat16* gA = g_zb + (size_t)(bm + arow) * 4096 + aoff + koff + half * 32;
    const __nv_bfloat16* gB = g_wb + (size_t)(bn + arow) * 4096 + boff + koff + half * 32;

    #define LOAD(ch) do { \
        const uint32_t sA_ = base + ((ch) % 3) * STG_B; \
        const uint32_t sB_ = sA_ + 8192; \
        const __nv_bfloat16* pa_ = gA + (ch) * 64; \
        const __nv_bfloat16* pb_ = gB + (ch) * 64; \
        _Pragma("unroll") \
        for (int j = 0; j < 4; j++) { cp16(sA_ + swo[j], pa_ + j * 8); cp16(sB_ + swo[j], pb_ + j * 8); } \
        asm volatile("cp.async.commit_group;" ::: "memory"); \
    } while (0)

    const uint32_t a_row = wm + (lane & 15);
    const uint32_t a_col = (lane >> 4) * 8;
    const uint32_t b_row = wn + (lane & 7) + ((lane >> 4) << 3);
    const uint32_t b_col = ((lane >> 3) & 1) * 8;

    float acc[2][4][4];
    #pragma unroll
    for (int mf = 0; mf < 2; mf++)
        #pragma unroll
        for (int nf = 0; nf < 4; nf++)
            #pragma unroll
            for (int e = 0; e < 4; e++) acc[mf][nf][e] = 0.f;

    LOAD(0);
    LOAD(1);

    for (int ch = 0; ch < NCH; ch++) {
        if (ch + 2 < NCH) {
            LOAD(ch + 2);
            asm volatile("cp.async.wait_group 2;" ::: "memory");
        } else if (ch + 1 < NCH) {
            asm volatile("cp.async.wait_group 1;" ::: "memory");
        } else {
            asm volatile("cp.async.wait_group 0;" ::: "memory");
        }
        __syncthreads();

        const uint32_t sA = base + (ch % 3) * STG_B;
        const uint32_t sB = sA + 8192;
        #pragma unroll
        for (int ks = 0; ks < 4; ks++) {
            uint32_t a[2][4], bfr[2][4];
            #pragma unroll
            for (int mf = 0; mf < 2; mf++)
                ldm4(a[mf], sA + SWZ((a_row + mf * 16) * 128 + (a_col + ks * 16) * 2));
            #pragma unroll
            for (int bg = 0; bg < 2; bg++)
                ldm4(bfr[bg], sB + SWZ((b_row + bg * 16) * 128 + (b_col + ks * 16) * 2));
            #pragma unroll
            for (int mf = 0; mf < 2; mf++) {
                mma16816(acc[mf][0], a[mf], bfr[0][0], bfr[0][1]);
                mma16816(acc[mf][1], a[mf], bfr[0][2], bfr[0][3]);
                mma16816(acc[mf][2], a[mf], bfr[1][0], bfr[1][1]);
                mma16816(acc[mf][3], a[mf], bfr[1][2], bfr[1][3]);
            }
        }
        __syncthreads();
    }
    #undef LOAD

    float* pp = g_part + (size_t)(pbase + zs) * 524288;
    const int gid = lane >> 2, cpo = 2 * (lane & 3);
    #pragma unroll
    for (int mf = 0; mf < 2; mf++) {
        const int row0 = bm + wm + mf * 16 + gid;
        #pragma unroll
        for (int nf = 0; nf < 4; nf++) {
            const int col = bn + wn + nf * 8 + cpo;
            *(float2*)(pp + (size_t)row0 * 2048 + col)       = make_float2(acc[mf][nf][0], acc[mf][nf][1]);
            *(float2*)(pp + (size_t)(row0 + 8) * 2048 + col) = make_float2(acc[mf][nf][2], acc[mf][nf][3]);
        }
    }
}

// ---------------------------------------------------------------------------
// Kernel 4: sum the 6 split partials into out.
// ---------------------------------------------------------------------------
__global__ __launch_bounds__(256) void k4_reduce(float* __restrict__ out)
{
    const int i = (blockIdx.x * 256 + threadIdx.x) * 4;
    float4 o = *(const float4*)(g_part + i);
    #pragma unroll
    for (int s = 1; s < 6; s++) {
        const float4 p = *(const float4*)(g_part + (size_t)s * 524288 + i);
        o.x += p.x; o.y += p.y; o.z += p.z; o.w += p.w;
    }
    *(float4*)(out + i) = o;
}

// ---------------------------------------------------------------------------
// Launch: output layout = concat(out (B*OC*OF), adj (B*C*F*F)) in fp32.
// Stream fork after k1b: side stream runs convW + convZ(x) + mma(x-half)
// concurrently with k2 (MUFU-bound) on the main stream. Streams/events are
// created on the first (uncaptured) call; fork-join via events is the
// documented capturable pattern. Fallback: if creation fails, s1 = stream 0
// (fully serial, still correct).
// ---------------------------------------------------------------------------
extern "C" void kernel_launch(void* const* d_in, const int* in_sizes, int n_in,
                              void* d_out, int out_size)
{
    const float* x   = (const float*)d_in[0];
    const float* nb  = (const float*)d_in[1];
    const float* Wa1 = (const float*)d_in[2];
    const float* Wa2 = (const float*)d_in[3];
    const float* Wc  = (const float*)d_in[4];
    float* out = (float*)d_out;
    float* adj = out + (size_t)B_ * OC_ * OF_;

    static cudaStream_t s1 = 0;
    static cudaEvent_t evFork = 0, evJoin = 0;
    static int init_done = 0;
    if (!init_done) {
        cudaFuncSetAttribute(k3_mma, cudaFuncAttributeMaxDynamicSharedMemorySize, K3_DSMEM);
        if (cudaStreamCreateWithFlags(&s1, cudaStreamNonBlocking) != cudaSuccess) s1 = 0;
        if (cudaEventCreateWithFlags(&evFork, cudaEventDisableTiming) != cudaSuccess) evFork = 0;
        if (cudaEventCreateWithFlags(&evJoin, cudaEventDisableTiming) != cudaSuccess) evJoin = 0;
        if (!evFork || !evJoin) s1 = 0;   // serial fallback
        init_done = 1;
    }

    k1a_logits<<<B_ * 4, 256>>>(nb, Wa2);
    k1b_softmax<<<B_, 256>>>(x, Wa1);

    if (s1) {
        cudaEventRecord(evFork, 0);
        cudaStreamWaitEvent(s1, evFork, 0);
    }
    // side stream: x-half GEMM chain (needs only k1b)
    k3a_convW<<<4096, 256, 0, s1>>>(Wc);
    k3b_convZ<<<256, 256, 0, s1>>>(1024);
    k3_mma<<<dim3(32, 4, 3), 128, K3_DSMEM, s1>>>(1024, 0);
    if (s1) cudaEventRecord(evJoin, s1);

    // main stream: adj + h, then h-half GEMM chain
    k2_adj<<<B_ * C_, 256>>>(x, nb, adj);
    k3b_convZ<<<256, 256>>>(0);
    k3_mma<<<dim3(32, 4, 3), 128, K3_DSMEM>>>(0, 3);

    if (s1) cudaStreamWaitEvent(0, evJoin, 0);
    k4_reduce<<<512, 256>>>(out);
}

// round 14
// speedup vs baseline: 1.1938x; 1.0339x over previous
#include <cuda_runtime.h>
#include <cuda_bf16.h>
#include <cstdint>
#include <cstddef>

#define B_  256
#define C_  4
#define N_  64
#define F_  256
#define OC_ 8
#define OF_ 256

typedef unsigned long long ull;

// Scratch (no allocations allowed)
__device__ float g_z[B_ * 2 * C_ * F_];                 // 2 MB : concat(h, x)
__device__ float g_w[B_ * N_];                          // softmax weights
__device__ float g_s2[B_ * N_];                         // raw neighbor logits
__device__ __nv_bfloat16 g_zb[B_ * 4096];               // 2 MB : z planes [hi|lo]
__device__ __nv_bfloat16 g_wb[2048 * 4096];             // 16 MB: W planes [hi|lo]
__device__ float g_part[3 * B_ * OC_ * OF_];            // 6 MB : split partials

__device__ __forceinline__ float sqrt_ap(float v) {
    float r; asm("sqrt.approx.f32 %0, %1;" : "=f"(r) : "f"(v)); return r;
}
__device__ __forceinline__ float rcp_ap(float v) {
    float r; asm("rcp.approx.f32 %0, %1;" : "=f"(r) : "f"(v)); return r;
}
__device__ __forceinline__ uint32_t smem_u32(const void* p) {
    uint32_t a;
    asm("{ .reg .u64 t; cvta.to.shared.u64 t, %1; cvt.u32.u64 %0, t; }" : "=r"(a) : "l"(p));
    return a;
}
__device__ __forceinline__ void cp16(uint32_t s, const void* g) {
    asm volatile("cp.async.cg.shared.global [%0], [%1], 16;" :: "r"(s), "l"(g));
}
#define SWZ(o) ((o) ^ (((o) >> 3) & 0x70))

__device__ __forceinline__ void ldm4(uint32_t* r, uint32_t addr) {
    asm volatile("ldmatrix.sync.aligned.m8n8.x4.shared.b16 {%0,%1,%2,%3}, [%4];"
        : "=r"(r[0]), "=r"(r[1]), "=r"(r[2]), "=r"(r[3]) : "r"(addr));
}
__device__ __forceinline__ void mma16816(float* c, const uint32_t* a, uint32_t b0, uint32_t b1) {
    asm volatile("mma.sync.aligned.m16n8k16.row.col.f32.bf16.bf16.f32 "
        "{%0,%1,%2,%3}, {%4,%5,%6,%7}, {%8,%9}, {%0,%1,%2,%3};"
        : "+f"(c[0]), "+f"(c[1]), "+f"(c[2]), "+f"(c[3])
        : "r"(a[0]), "r"(a[1]), "r"(a[2]), "r"(a[3]), "r"(b0), "r"(b1));
}

// ---------------------------------------------------------------------------
// Kernel 1a: s2 logits. Grid 1024.
// ---------------------------------------------------------------------------
__global__ __launch_bounds__(256) void k1a_logits(
    const float* __restrict__ nb, const float* __restrict__ Wa2)
{
    __shared__ float ws2[256];
    const int b = blockIdx.x >> 2, quarter = blockIdx.x & 3;
    const int t = threadIdx.x;
    const int lane = t & 31, w = t >> 5;

    ws2[t] = Wa2[t] + Wa2[256 + t] + Wa2[512 + t] + Wa2[768 + t];
    __syncthreads();

    const float* nbb = nb + (size_t)b * 65536;
    #pragma unroll
    for (int j = 0; j < 2; j++) {
        const int n = quarter * 16 + w * 2 + j;
        const float4* np = (const float4*)(nbb + n * 1024);
        float acc = 0.f;
        #pragma unroll
        for (int it = 0; it < 8; it++) {
            float4 q = np[it * 32 + lane];
            int f = (it * 128 + lane * 4) & 255;
            acc += q.x * ws2[f] + q.y * ws2[f + 1] + q.z * ws2[f + 2] + q.w * ws2[f + 3];
        }
        #pragma unroll
        for (int o = 16; o > 0; o >>= 1) acc += __shfl_xor_sync(0xffffffffu, acc, o);
        if (lane == 0) g_s2[b * 64 + n] = acc;
    }
}

// ---------------------------------------------------------------------------
// Kernel 1b: s1 + softmax; copy x into z channels 4..7.
// ---------------------------------------------------------------------------
__global__ __launch_bounds__(256) void k1b_softmax(
    const float* __restrict__ x, const float* __restrict__ Wa1)
{
    __shared__ float red[8];
    const int b = blockIdx.x;
    const int t = threadIdx.x;
    const int lane = t & 31, w = t >> 5;

    float w1 = Wa1[t] + Wa1[256 + t] + Wa1[512 + t] + Wa1[768 + t];

    float xs = 0.f;
    #pragma unroll
    for (int c = 0; c < 4; c++) {
        float xv = x[(b * 4 + c) * 256 + t];
        g_z[b * 2048 + (4 + c) * 256 + t] = xv;
        xs += xv;
    }
    float p = xs * w1;
    #pragma unroll
    for (int o = 16; o > 0; o >>= 1) p += __shfl_xor_sync(0xffffffffu, p, o);
    if (lane == 0) red[w] = p;
    __syncthreads();

    if (w == 0) {
        float s1v = red[lane & 7];
        #pragma unroll
        for (int o = 4; o > 0; o >>= 1) s1v += __shfl_xor_sync(0xffffffffu, s1v, o);
        float l0 = s1v * g_s2[b * 64 + lane];
        float l1 = s1v * g_s2[b * 64 + lane + 32];
        float m = fmaxf(l0, l1);
        #pragma unroll
        for (int o = 16; o > 0; o >>= 1) m = fmaxf(m, __shfl_xor_sync(0xffffffffu, m, o));
        float e0 = __expf(l0 - m), e1 = __expf(l1 - m);
        float s = e0 + e1;
        #pragma unroll
        for (int o = 16; o > 0; o >>= 1) s += __shfl_xor_sync(0xffffffffu, s, o);
        float inv = 1.f / s;
        g_w[b * 64 + lane]      = e0 * inv;
        g_w[b * 64 + lane + 32] = e1 * inv;
    }
}

// ---------------------------------------------------------------------------
// Kernel 2: v + adj + fused h (round-12 measured version, unchanged).
// ---------------------------------------------------------------------------
__global__ __launch_bounds__(256) void k2_adj(
    const float* __restrict__ x, const float* __restrict__ nb,
    float* __restrict__ adj)
{
    __shared__ float xs[256], vs[256], us[256], idn[256];
    __shared__ float wsm[64];
    __shared__ float pden[4 * 256];

    const int bc = blockIdx.x;
    const int b = bc >> 2, c = bc & 3;
    const int t = threadIdx.x;

    if (t < 64) wsm[t] = g_w[b * 64 + t];
    xs[t] = x[bc * 256 + t];
    __syncthreads();

    {
        const float* nbp = nb + ((size_t)b * 256 + c) * 256 + t;
        float acc = 0.f;
        #pragma unroll 8
        for (int n = 0; n < 64; n++) acc += wsm[n] * nbp[(size_t)n * 1024];
        vs[t] = acc;
    }
    __syncthreads();

    const int r = t >> 6, cg = t & 63;
    const int i0 = r * 64;
    float xc[4], vc[4];
    #pragma unroll
    for (int j = 0; j < 4; j++) { xc[j] = xs[4 * cg + j]; vc[j] = vs[4 * cg + j]; }

    float d[4] = {0.f, 0.f, 0.f, 0.f};
    #pragma unroll 4
    for (int ii = 0; ii < 64; ii++) {
        const int i = i0 + ii;
        const float xi = xs[i], vi = vs[i];
        #pragma unroll
        for (int j = 0; j < 4; j++) {
            float tv = xi * vc[j] + xc[j] * vi;
            d[j] += sqrt_ap(fmaxf(fabsf(tv), 1e-8f));
        }
    }
    #pragma unroll
    for (int j = 0; j < 4; j++) pden[r * 256 + 4 * cg + j] = d[j];
    __syncthreads();

    {
        float den = pden[t] + pden[256 + t] + pden[512 + t] + pden[768 + t];
        float id = rcp_ap(den + 1e-7f);
        idn[t] = id;
        us[t] = xs[t] * id;
    }
    __syncthreads();

    float ic[4];
    #pragma unroll
    for (int j = 0; j < 4; j++) ic[j] = idn[4 * cg + j];
    float h[4] = {0.f, 0.f, 0.f, 0.f};
    float* ap = adj + (size_t)bc * 65536 + 4 * cg;

    #pragma unroll 4
    for (int ii = 0; ii < 64; ii++) {
        const int i = i0 + ii;
        const float xi = xs[i], vi = vs[i], usi = us[i];
        float4 o;
        #pragma unroll
        for (int j = 0; j < 4; j++) {
            float tv = xi * vc[j] + xc[j] * vi;
            float a = copysignf(sqrt_ap(fmaxf(fabsf(tv), 1e-8f)), tv);
            (&o.x)[j] = a * ic[j];
            h[j] = fmaf(a, usi, h[j]);
        }
        __stcs((float4*)(ap + (size_t)i * 256), o);
    }
    #pragma unroll
    for (int j = 0; j < 4; j++) pden[r * 256 + 4 * cg + j] = h[j];
    __syncthreads();

    float hs = pden[t] + pden[256 + t] + pden[512 + t] + pden[768 + t];
    g_z[b * 2048 + c * 256 + t] = hs;
}

// ---------------------------------------------------------------------------
// Kernels 3a/3b: fp32 -> bf16 two planes [hi | lo].
// ---------------------------------------------------------------------------
__global__ __launch_bounds__(256) void k3a_convW(const float* __restrict__ src)
{
    const size_t idx = ((size_t)blockIdx.x * 256 + threadIdx.x) * 4;
    const int r = (int)(idx >> 11), k = (int)(idx & 2047);
    const float4 v = *(const float4*)(src + idx);
    ull hv = 0, lv = 0;
    #pragma unroll
    for (int j = 0; j < 4; j++) {
        float f = (&v.x)[j];
        __nv_bfloat16 hb = __float2bfloat16(f);
        __nv_bfloat16 lb = __float2bfloat16(f - __bfloat162float(hb));
        hv |= (ull)__bfloat16_as_ushort(hb) << (16 * j);
        lv |= (ull)__bfloat16_as_ushort(lb) << (16 * j);
    }
    __nv_bfloat16* dst = g_wb + (size_t)r * 4096 + k;
    *(ull*)dst          = hv;
    *(ull*)(dst + 2048) = lv;
}

__global__ __launch_bounds__(256) void k3b_convZ(void)
{
    const size_t idx = ((size_t)blockIdx.x * 256 + threadIdx.x) * 4;
    const int r = (int)(idx >> 11), k = (int)(idx & 2047);
    const float4 v = *(const float4*)(g_z + idx);
    ull hv = 0, lv = 0;
    #pragma unroll
    for (int j = 0; j < 4; j++) {
        float f = (&v.x)[j];
        __nv_bfloat16 hb = __float2bfloat16(f);
        __nv_bfloat16 lb = __float2bfloat16(f - __bfloat162float(hb));
        hv |= (ull)__bfloat16_as_ushort(hb) << (16 * j);
        lv |= (ull)__bfloat16_as_ushort(lb) << (16 * j);
    }
    __nv_bfloat16* dst = g_zb + (size_t)r * 4096 + k;
    *(ull*)dst          = hv;
    *(ull*)(dst + 2048) = lv;
}

// ---------------------------------------------------------------------------
// Kernel 3: mma.sync bf16 GEMM, split by plane product (z: 0 hi*hi, 1 lo*hi,
// 2 hi*lo), K=2048 each (32 chunks). 4-stage cp.async pipeline with ONE
// __syncthreads per chunk; __launch_bounds__(128,3) pins >=3 CTAs/SM
// (12 warps/SM; 4x16KB stages x 3 CTAs = 195KB smem).
// ---------------------------------------------------------------------------
#define NCH 32
#define STG_B 16384
#define K3_DSMEM (4 * STG_B + 1024)

__global__ __launch_bounds__(128, 3) void k3_mma(void)
{
    extern __shared__ char dsm[];
    const int t = threadIdx.x, wid = t >> 5, lane = t & 31;
    const int bn = blockIdx.x * 64, bm = blockIdx.y * 64, zs = blockIdx.z;
    const uint32_t base = (smem_u32(dsm) + 1023) & ~1023u;

    const int aoff = (zs == 1) ? 2048 : 0;
    const int boff = (zs == 2) ? 2048 : 0;
    const int wm = (wid & 1) * 32, wn = (wid >> 1) * 32;

    const int arow = t & 63, half = t >> 6;
    uint32_t swo[4];
    #pragma unroll
    for (int j = 0; j < 4; j++) swo[j] = SWZ((uint32_t)(arow * 128 + half * 64 + j * 16));
    const __nv_bfloat16* gA = g_zb + (size_t)(bm + arow) * 4096 + aoff + half * 32;
    const __nv_bfloat16* gB = g_wb + (size_t)(bn + arow) * 4096 + boff + half * 32;

    #define LOAD(ch) do { \
        const uint32_t sA_ = base + ((ch) & 3) * STG_B; \
        const uint32_t sB_ = sA_ + 8192; \
        const __nv_bfloat16* pa_ = gA + (ch) * 64; \
        const __nv_bfloat16* pb_ = gB + (ch) * 64; \
        _Pragma("unroll") \
        for (int j = 0; j < 4; j++) { cp16(sA_ + swo[j], pa_ + j * 8); cp16(sB_ + swo[j], pb_ + j * 8); } \
        asm volatile("cp.async.commit_group;" ::: "memory"); \
    } while (0)

    const uint32_t a_row = wm + (lane & 15);
    const uint32_t a_col = (lane >> 4) * 8;
    const uint32_t b_row = wn + (lane & 7) + ((lane >> 4) << 3);
    const uint32_t b_col = ((lane >> 3) & 1) * 8;

    float acc[2][4][4];
    #pragma unroll
    for (int mf = 0; mf < 2; mf++)
        #pragma unroll
        for (int nf = 0; nf < 4; nf++)
            #pragma unroll
            for (int e = 0; e < 4; e++) acc[mf][nf][e] = 0.f;

    LOAD(0);
    LOAD(1);
    LOAD(2);

    for (int ch = 0; ch < NCH; ch++) {
        // chunk ch complete when pending groups <= (commits_so_far - ch - 1)
        if (ch < NCH - 2)       asm volatile("cp.async.wait_group 2;" ::: "memory");
        else if (ch == NCH - 2) asm volatile("cp.async.wait_group 1;" ::: "memory");
        else                    asm volatile("cp.async.wait_group 0;" ::: "memory");
        // single barrier: (a) data of chunk ch visible to all threads,
        // (b) all reads of buffer (ch-1)&3 done before LOAD(ch+3) overwrites it
        __syncthreads();
        if (ch + 3 < NCH) LOAD(ch + 3);

        const uint32_t sA = base + (ch & 3) * STG_B;
        const uint32_t sB = sA + 8192;
        #pragma unroll
        for (int ks = 0; ks < 4; ks++) {
            uint32_t a[2][4], bfr[2][4];
            #pragma unroll
            for (int mf = 0; mf < 2; mf++)
                ldm4(a[mf], sA + SWZ((a_row + mf * 16) * 128 + (a_col + ks * 16) * 2));
            #pragma unroll
            for (int bg = 0; bg < 2; bg++)
                ldm4(bfr[bg], sB + SWZ((b_row + bg * 16) * 128 + (b_col + ks * 16) * 2));
            #pragma unroll
            for (int mf = 0; mf < 2; mf++) {
                mma16816(acc[mf][0], a[mf], bfr[0][0], bfr[0][1]);
                mma16816(acc[mf][1], a[mf], bfr[0][2], bfr[0][3]);
                mma16816(acc[mf][2], a[mf], bfr[1][0], bfr[1][1]);
                mma16816(acc[mf][3], a[mf], bfr[1][2], bfr[1][3]);
            }
        }
    }
    #undef LOAD

    float* pp = g_part + (size_t)zs * 524288;
    const int gid = lane >> 2, cpo = 2 * (lane & 3);
    #pragma unroll
    for (int mf = 0; mf < 2; mf++) {
        const int row0 = bm + wm + mf * 16 + gid;
        #pragma unroll
        for (int nf = 0; nf < 4; nf++) {
            const int col = bn + wn + nf * 8 + cpo;
            *(float2*)(pp + (size_t)row0 * 2048 + col)       = make_float2(acc[mf][nf][0], acc[mf][nf][1]);
            *(float2*)(pp + (size_t)(row0 + 8) * 2048 + col) = make_float2(acc[mf][nf][2], acc[mf][nf][3]);
        }
    }
}

// ---------------------------------------------------------------------------
// Kernel 4: sum the 3 split partials into out.
// ---------------------------------------------------------------------------
__global__ __launch_bounds__(256) void k4_reduce(float* __restrict__ out)
{
    const int i = (blockIdx.x * 256 + threadIdx.x) * 4;
    const float4 p0 = *(const float4*)(g_part + i);
    const float4 p1 = *(const float4*)(g_part + 524288 + i);
    const float4 p2 = *(const float4*)(g_part + 2 * 524288 + i);
    float4 o;
    o.x = p0.x + p1.x + p2.x;
    o.y = p0.y + p1.y + p2.y;
    o.z = p0.z + p1.z + p2.z;
    o.w = p0.w + p1.w + p2.w;
    *(float4*)(out + i) = o;
}

// ---------------------------------------------------------------------------
// Launch: output layout = concat(out (B*OC*OF), adj (B*C*F*F)) in fp32.
// convW runs on a side stream under k2 (pure side work); everything else
// serial — round-13 showed the split-mma fork gains nothing (k2 fills SMs).
// ---------------------------------------------------------------------------
extern "C" void kernel_launch(void* const* d_in, const int* in_sizes, int n_in,
                              void* d_out, int out_size)
{
    const float* x   = (const float*)d_in[0];
    const float* nb  = (const float*)d_in[1];
    const float* Wa1 = (const float*)d_in[2];
    const float* Wa2 = (const float*)d_in[3];
    const float* Wc  = (const float*)d_in[4];
    float* out = (float*)d_out;
    float* adj = out + (size_t)B_ * OC_ * OF_;

    static cudaStream_t s1 = 0;
    static cudaEvent_t evFork = 0, evJoin = 0;
    static int init_done = 0;
    if (!init_done) {
        cudaFuncSetAttribute(k3_mma, cudaFuncAttributeMaxDynamicSharedMemorySize, K3_DSMEM);
        if (cudaStreamCreateWithFlags(&s1, cudaStreamNonBlocking) != cudaSuccess) s1 = 0;
        if (cudaEventCreateWithFlags(&evFork, cudaEventDisableTiming) != cudaSuccess) evFork = 0;
        if (cudaEventCreateWithFlags(&evJoin, cudaEventDisableTiming) != cudaSuccess) evJoin = 0;
        if (!evFork || !evJoin) s1 = 0;   // serial fallback
        init_done = 1;
    }

    k1a_logits<<<B_ * 4, 256>>>(nb, Wa2);
    k1b_softmax<<<B_, 256>>>(x, Wa1);

    if (s1) {
        cudaEventRecord(evFork, 0);
        cudaStreamWaitEvent(s1, evFork, 0);
    }
    k3a_convW<<<4096, 256, 0, s1>>>(Wc);       // side: overlaps k2
    if (s1) cudaEventRecord(evJoin, s1);

    k2_adj<<<B_ * C_, 256>>>(x, nb, adj);
    k3b_convZ<<<512, 256>>>();
    if (s1) cudaStreamWaitEvent(0, evJoin, 0);
    k3_mma<<<dim3(32, 4, 3), 128, K3_DSMEM>>>();
    k4_reduce<<<512, 256>>>(out);
}

// round 15
// speedup vs baseline: 1.2603x; 1.0557x over previous
#include <cuda_runtime.h>
#include <cuda_bf16.h>
#include <cstdint>
#include <cstddef>

#define B_  256
#define C_  4
#define N_  64
#define F_  256
#define OC_ 8
#define OF_ 256

typedef unsigned long long ull;

// Scratch (no allocations allowed)
__device__ float g_w[B_ * N_];                          // softmax weights
__device__ float g_s2[B_ * N_];                         // raw neighbor logits
__device__ __nv_bfloat16 g_zb[B_ * 4096];               // 2 MB : z planes [hi|lo]
__device__ __nv_bfloat16 g_wb[2048 * 4096];             // 16 MB: W planes [hi|lo]
__device__ float g_part[3 * B_ * OC_ * OF_];            // 6 MB : split partials

__device__ __forceinline__ float sqrt_ap(float v) {
    float r; asm("sqrt.approx.f32 %0, %1;" : "=f"(r) : "f"(v)); return r;
}
__device__ __forceinline__ float rcp_ap(float v) {
    float r; asm("rcp.approx.f32 %0, %1;" : "=f"(r) : "f"(v)); return r;
}
__device__ __forceinline__ uint32_t smem_u32(const void* p) {
    uint32_t a;
    asm("{ .reg .u64 t; cvta.to.shared.u64 t, %1; cvt.u32.u64 %0, t; }" : "=r"(a) : "l"(p));
    return a;
}
__device__ __forceinline__ void cp16(uint32_t s, const void* g) {
    asm volatile("cp.async.cg.shared.global [%0], [%1], 16;" :: "r"(s), "l"(g));
}
#define SWZ(o) ((o) ^ (((o) >> 3) & 0x70))

__device__ __forceinline__ void ldm4(uint32_t* r, uint32_t addr) {
    asm volatile("ldmatrix.sync.aligned.m8n8.x4.shared.b16 {%0,%1,%2,%3}, [%4];"
        : "=r"(r[0]), "=r"(r[1]), "=r"(r[2]), "=r"(r[3]) : "r"(addr));
}
__device__ __forceinline__ void mma16816(float* c, const uint32_t* a, uint32_t b0, uint32_t b1) {
    asm volatile("mma.sync.aligned.m16n8k16.row.col.f32.bf16.bf16.f32 "
        "{%0,%1,%2,%3}, {%4,%5,%6,%7}, {%8,%9}, {%0,%1,%2,%3};"
        : "+f"(c[0]), "+f"(c[1]), "+f"(c[2]), "+f"(c[3])
        : "r"(a[0]), "r"(a[1]), "r"(a[2]), "r"(a[3]), "r"(b0), "r"(b1));
}
__device__ __forceinline__ void split_bf16(float f, __nv_bfloat16& hb, __nv_bfloat16& lb) {
    hb = __float2bfloat16(f);
    lb = __float2bfloat16(f - __bfloat162float(hb));
}

// ---------------------------------------------------------------------------
// Kernel 1a: s2 logits. Grid 1024.
// ---------------------------------------------------------------------------
__global__ __launch_bounds__(256) void k1a_logits(
    const float* __restrict__ nb, const float* __restrict__ Wa2)
{
    __shared__ float ws2[256];
    const int b = blockIdx.x >> 2, quarter = blockIdx.x & 3;
    const int t = threadIdx.x;
    const int lane = t & 31, w = t >> 5;

    ws2[t] = Wa2[t] + Wa2[256 + t] + Wa2[512 + t] + Wa2[768 + t];
    __syncthreads();

    const float* nbb = nb + (size_t)b * 65536;
    #pragma unroll
    for (int j = 0; j < 2; j++) {
        const int n = quarter * 16 + w * 2 + j;
        const float4* np = (const float4*)(nbb + n * 1024);
        float acc = 0.f;
        #pragma unroll
        for (int it = 0; it < 8; it++) {
            float4 q = np[it * 32 + lane];
            int f = (it * 128 + lane * 4) & 255;
            acc += q.x * ws2[f] + q.y * ws2[f + 1] + q.z * ws2[f + 2] + q.w * ws2[f + 3];
        }
        #pragma unroll
        for (int o = 16; o > 0; o >>= 1) acc += __shfl_xor_sync(0xffffffffu, acc, o);
        if (lane == 0) g_s2[b * 64 + n] = acc;
    }
}

// ---------------------------------------------------------------------------
// Kernel 1b: s1 + softmax; write x directly as bf16 planes (channels 4..7).
// ---------------------------------------------------------------------------
__global__ __launch_bounds__(256) void k1b_softmax(
    const float* __restrict__ x, const float* __restrict__ Wa1)
{
    __shared__ float red[8];
    const int b = blockIdx.x;
    const int t = threadIdx.x;
    const int lane = t & 31, w = t >> 5;

    float w1 = Wa1[t] + Wa1[256 + t] + Wa1[512 + t] + Wa1[768 + t];

    float xs = 0.f;
    #pragma unroll
    for (int c = 0; c < 4; c++) {
        float xv = x[(b * 4 + c) * 256 + t];
        __nv_bfloat16 hb, lb;
        split_bf16(xv, hb, lb);
        const int k = (4 + c) * 256 + t;
        g_zb[b * 4096 + k]        = hb;
        g_zb[b * 4096 + 2048 + k] = lb;
        xs += xv;
    }
    float p = xs * w1;
    #pragma unroll
    for (int o = 16; o > 0; o >>= 1) p += __shfl_xor_sync(0xffffffffu, p, o);
    if (lane == 0) red[w] = p;
    __syncthreads();

    if (w == 0) {
        float s1v = red[lane & 7];
        #pragma unroll
        for (int o = 4; o > 0; o >>= 1) s1v += __shfl_xor_sync(0xffffffffu, s1v, o);
        float l0 = s1v * g_s2[b * 64 + lane];
        float l1 = s1v * g_s2[b * 64 + lane + 32];
        float m = fmaxf(l0, l1);
        #pragma unroll
        for (int o = 16; o > 0; o >>= 1) m = fmaxf(m, __shfl_xor_sync(0xffffffffu, m, o));
        float e0 = __expf(l0 - m), e1 = __expf(l1 - m);
        float s = e0 + e1;
        #pragma unroll
        for (int o = 16; o > 0; o >>= 1) s += __shfl_xor_sync(0xffffffffu, s, o);
        float inv = 1.f / s;
        g_w[b * 64 + lane]      = e0 * inv;
        g_w[b * 64 + lane + 32] = e1 * inv;
    }
}

// ---------------------------------------------------------------------------
// Kernel 2: v + adj + fused h. v-phase vectorized (16x LDG.128 per thread,
// 4-way smem reduce). h written directly as bf16 planes (channels 0..3).
// ---------------------------------------------------------------------------
__global__ __launch_bounds__(256) void k2_adj(
    const float* __restrict__ x, const float* __restrict__ nb,
    float* __restrict__ adj)
{
    __shared__ float xs[256], vs[256], us[256], idn[256];
    __shared__ float wsm[64];
    __shared__ float pden[4 * 256];

    const int bc = blockIdx.x;
    const int b = bc >> 2, c = bc & 3;
    const int t = threadIdx.x;

    if (t < 64) wsm[t] = g_w[b * 64 + t];
    xs[t] = x[bc * 256 + t];
    __syncthreads();

    // v-phase: thread (ng, fg) accumulates float4 over its 16 n's
    {
        const int fg = t & 63, ng = t >> 6;
        const float4* np4 = (const float4*)(nb + (size_t)b * 65536 + c * 256) + fg;
        float4 a4 = make_float4(0.f, 0.f, 0.f, 0.f);
        #pragma unroll 4
        for (int n = ng * 16; n < ng * 16 + 16; n++) {
            const float wn = wsm[n];
            const float4 q = np4[(size_t)n * 256];
            a4.x += wn * q.x; a4.y += wn * q.y; a4.z += wn * q.z; a4.w += wn * q.w;
        }
        *(float4*)&pden[ng * 256 + fg * 4] = a4;
    }
    __syncthreads();
    vs[t] = pden[t] + pden[256 + t] + pden[512 + t] + pden[768 + t];
    __syncthreads();

    const int r = t >> 6, cg = t & 63;
    const int i0 = r * 64;
    float xc[4], vc[4];
    #pragma unroll
    for (int j = 0; j < 4; j++) { xc[j] = xs[4 * cg + j]; vc[j] = vs[4 * cg + j]; }

    float d[4] = {0.f, 0.f, 0.f, 0.f};
    #pragma unroll 4
    for (int ii = 0; ii < 64; ii++) {
        const int i = i0 + ii;
        const float xi = xs[i], vi = vs[i];
        #pragma unroll
        for (int j = 0; j < 4; j++) {
            float tv = xi * vc[j] + xc[j] * vi;
            d[j] += sqrt_ap(fmaxf(fabsf(tv), 1e-8f));
        }
    }
    #pragma unroll
    for (int j = 0; j < 4; j++) pden[r * 256 + 4 * cg + j] = d[j];
    __syncthreads();

    {
        float den = pden[t] + pden[256 + t] + pden[512 + t] + pden[768 + t];
        float id = rcp_ap(den + 1e-7f);
        idn[t] = id;
        us[t] = xs[t] * id;
    }
    __syncthreads();

    float ic[4];
    #pragma unroll
    for (int j = 0; j < 4; j++) ic[j] = idn[4 * cg + j];
    float h[4] = {0.f, 0.f, 0.f, 0.f};
    float* ap = adj + (size_t)bc * 65536 + 4 * cg;

    #pragma unroll 4
    for (int ii = 0; ii < 64; ii++) {
        const int i = i0 + ii;
        const float xi = xs[i], vi = vs[i], usi = us[i];
        float4 o;
        #pragma unroll
        for (int j = 0; j < 4; j++) {
            float tv = xi * vc[j] + xc[j] * vi;
            float a = copysignf(sqrt_ap(fmaxf(fabsf(tv), 1e-8f)), tv);
            (&o.x)[j] = a * ic[j];
            h[j] = fmaf(a, usi, h[j]);
        }
        __stcs((float4*)(ap + (size_t)i * 256), o);
    }
    #pragma unroll
    for (int j = 0; j < 4; j++) pden[r * 256 + 4 * cg + j] = h[j];
    __syncthreads();

    float hs = pden[t] + pden[256 + t] + pden[512 + t] + pden[768 + t];
    __nv_bfloat16 hb, lb;
    split_bf16(hs, hb, lb);
    const int k = c * 256 + t;
    g_zb[b * 4096 + k]        = hb;
    g_zb[b * 4096 + 2048 + k] = lb;
}

// ---------------------------------------------------------------------------
// Kernel 3a: W fp32 -> bf16 planes [hi | lo].
// ---------------------------------------------------------------------------
__global__ __launch_bounds__(256) void k3a_convW(const float* __restrict__ src)
{
    const size_t idx = ((size_t)blockIdx.x * 256 + threadIdx.x) * 4;
    const int r = (int)(idx >> 11), k = (int)(idx & 2047);
    const float4 v = *(const float4*)(src + idx);
    ull hv = 0, lv = 0;
    #pragma unroll
    for (int j = 0; j < 4; j++) {
        __nv_bfloat16 hb, lb;
        split_bf16((&v.x)[j], hb, lb);
        hv |= (ull)__bfloat16_as_ushort(hb) << (16 * j);
        lv |= (ull)__bfloat16_as_ushort(lb) << (16 * j);
    }
    __nv_bfloat16* dst = g_wb + (size_t)r * 4096 + k;
    *(ull*)dst          = hv;
    *(ull*)(dst + 2048) = lv;
}

// ---------------------------------------------------------------------------
// Kernel 3: mma.sync bf16 GEMM, split by plane product (z: 0 hi*hi, 1 lo*hi,
// 2 hi*lo), K=2048 each. 3-stage cp.async, one __syncthreads per chunk,
// __launch_bounds__(128,4): 4 CTAs/SM = 16 warps/SM (3x16KB+1K stages x4 =
// 200KB smem/SM).
// ---------------------------------------------------------------------------
#define NCH 32
#define STG_B 16384
#define K3_DSMEM (3 * STG_B + 1024)

__global__ __launch_bounds__(128, 4) void k3_mma(void)
{
    extern __shared__ char dsm[];
    const int t = threadIdx.x, wid = t >> 5, lane = t & 31;
    const int bn = blockIdx.x * 64, bm = blockIdx.y * 64, zs = blockIdx.z;
    const uint32_t base = (smem_u32(dsm) + 1023) & ~1023u;

    const int aoff = (zs == 1) ? 2048 : 0;
    const int boff = (zs == 2) ? 2048 : 0;
    const int wm = (wid & 1) * 32, wn = (wid >> 1) * 32;

    const int arow = t & 63, half = t >> 6;
    uint32_t swo[4];
    #pragma unroll
    for (int j = 0; j < 4; j++) swo[j] = SWZ((uint32_t)(arow * 128 + half * 64 + j * 16));
    const __nv_bfloat16* gA = g_zb + (size_t)(bm + arow) * 4096 + aoff + half * 32;
    const __nv_bfloat16* gB = g_wb + (size_t)(bn + arow) * 4096 + boff + half * 32;

    #define LOAD(ch) do { \
        const uint32_t sA_ = base + ((ch) % 3) * STG_B; \
        const uint32_t sB_ = sA_ + 8192; \
        const __nv_bfloat16* pa_ = gA + (ch) * 64; \
        const __nv_bfloat16* pb_ = gB + (ch) * 64; \
        _Pragma("unroll") \
        for (int j = 0; j < 4; j++) { cp16(sA_ + swo[j], pa_ + j * 8); cp16(sB_ + swo[j], pb_ + j * 8); } \
        asm volatile("cp.async.commit_group;" ::: "memory"); \
    } while (0)

    const uint32_t a_row = wm + (lane & 15);
    const uint32_t a_col = (lane >> 4) * 8;
    const uint32_t b_row = wn + (lane & 7) + ((lane >> 4) << 3);
    const uint32_t b_col = ((lane >> 3) & 1) * 8;

    float acc[2][4][4];
    #pragma unroll
    for (int mf = 0; mf < 2; mf++)
        #pragma unroll
        for (int nf = 0; nf < 4; nf++)
            #pragma unroll
            for (int e = 0; e < 4; e++) acc[mf][nf][e] = 0.f;

    LOAD(0);
    LOAD(1);

    for (int ch = 0; ch < NCH; ch++) {
        // chunk ch is commit #ch; allowing 1 pending leaves only #ch+1 in flight
        if (ch < NCH - 1) asm volatile("cp.async.wait_group 1;" ::: "memory");
        else              asm volatile("cp.async.wait_group 0;" ::: "memory");
        // single barrier: data of chunk ch visible everywhere; all reads of
        // buffer (ch+2)%3 (= chunk ch-1) finished before LOAD(ch+2) overwrites
        __syncthreads();
        if (ch + 2 < NCH) LOAD(ch + 2);

        const uint32_t sA = base + (ch % 3) * STG_B;
        const uint32_t sB = sA + 8192;
        #pragma unroll
        for (int ks = 0; ks < 4; ks++) {
            uint32_t a[2][4], bfr[2][4];
            #pragma unroll
            for (int mf = 0; mf < 2; mf++)
                ldm4(a[mf], sA + SWZ((a_row + mf * 16) * 128 + (a_col + ks * 16) * 2));
            #pragma unroll
            for (int bg = 0; bg < 2; bg++)
                ldm4(bfr[bg], sB + SWZ((b_row + bg * 16) * 128 + (b_col + ks * 16) * 2));
            #pragma unroll
            for (int mf = 0; mf < 2; mf++) {
                mma16816(acc[mf][0], a[mf], bfr[0][0], bfr[0][1]);
                mma16816(acc[mf][1], a[mf], bfr[0][2], bfr[0][3]);
                mma16816(acc[mf][2], a[mf], bfr[1][0], bfr[1][1]);
                mma16816(acc[mf][3], a[mf], bfr[1][2], bfr[1][3]);
            }
        }
    }
    #undef LOAD

    float* pp = g_part + (size_t)zs * 524288;
    const int gid = lane >> 2, cpo = 2 * (lane & 3);
    #pragma unroll
    for (int mf = 0; mf < 2; mf++) {
        const int row0 = bm + wm + mf * 16 + gid;
        #pragma unroll
        for (int nf = 0; nf < 4; nf++) {
            const int col = bn + wn + nf * 8 + cpo;
            *(float2*)(pp + (size_t)row0 * 2048 + col)       = make_float2(acc[mf][nf][0], acc[mf][nf][1]);
            *(float2*)(pp + (size_t)(row0 + 8) * 2048 + col) = make_float2(acc[mf][nf][2], acc[mf][nf][3]);
        }
    }
}

// ---------------------------------------------------------------------------
// Kernel 4: sum the 3 split partials into out.
// ---------------------------------------------------------------------------
__global__ __launch_bounds__(256) void k4_reduce(float* __restrict__ out)
{
    const int i = (blockIdx.x * 256 + threadIdx.x) * 4;
    const float4 p0 = *(const float4*)(g_part + i);
    const float4 p1 = *(const float4*)(g_part + 524288 + i);
    const float4 p2 = *(const float4*)(g_part + 2 * 524288 + i);
    float4 o;
    o.x = p0.x + p1.x + p2.x;
    o.y = p0.y + p1.y + p2.y;
    o.z = p0.z + p1.z + p2.z;
    o.w = p0.w + p1.w + p2.w;
    *(float4*)(out + i) = o;
}

// ---------------------------------------------------------------------------
// Launch: output layout = concat(out (B*OC*OF), adj (B*C*F*F)) in fp32.
// convW overlaps k2 on a side stream; rest serial.
// ---------------------------------------------------------------------------
extern "C" void kernel_launch(void* const* d_in, const int* in_sizes, int n_in,
                              void* d_out, int out_size)
{
    const float* x   = (const float*)d_in[0];
    const float* nb  = (const float*)d_in[1];
    const float* Wa1 = (const float*)d_in[2];
    const float* Wa2 = (const float*)d_in[3];
    const float* Wc  = (const float*)d_in[4];
    float* out = (float*)d_out;
    float* adj = out + (size_t)B_ * OC_ * OF_;

    static cudaStream_t s1 = 0;
    static cudaEvent_t evFork = 0, evJoin = 0;
    static int init_done = 0;
    if (!init_done) {
        cudaFuncSetAttribute(k3_mma, cudaFuncAttributeMaxDynamicSharedMemorySize, K3_DSMEM);
        if (cudaStreamCreateWithFlags(&s1, cudaStreamNonBlocking) != cudaSuccess) s1 = 0;
        if (cudaEventCreateWithFlags(&evFork, cudaEventDisableTiming) != cudaSuccess) evFork = 0;
        if (cudaEventCreateWithFlags(&evJoin, cudaEventDisableTiming) != cudaSuccess) evJoin = 0;
        if (!evFork || !evJoin) s1 = 0;   // serial fallback
        init_done = 1;
    }

    k1a_logits<<<B_ * 4, 256>>>(nb, Wa2);
    k1b_softmax<<<B_, 256>>>(x, Wa1);

    if (s1) {
        cudaEventRecord(evFork, 0);
        cudaStreamWaitEvent(s1, evFork, 0);
    }
    k3a_convW<<<4096, 256, 0, s1>>>(Wc);       // side: overlaps k2
    if (s1) cudaEventRecord(evJoin, s1);

    k2_adj<<<B_ * C_, 256>>>(x, nb, adj);
    if (s1) cudaStreamWaitEvent(0, evJoin, 0);
    k3_mma<<<dim3(32, 4, 3), 128, K3_DSMEM>>>();
    k4_reduce<<<512, 256>>>(out);
}

// round 16
// speedup vs baseline: 1.5313x; 1.2151x over previous
#include <cuda_runtime.h>
#include <cuda_bf16.h>
#include <cstdint>
#include <cstddef>

#define B_  256
#define C_  4
#define N_  64
#define F_  256
#define OC_ 8
#define OF_ 256

typedef unsigned long long ull;

// Scratch (no allocations allowed)
__device__ float g_w[B_ * N_];                          // softmax weights
__device__ float g_s2[B_ * N_];                         // raw neighbor logits
__device__ __nv_bfloat16 g_zb[B_ * 4096];               // 2 MB : z planes [hi|lo]
__device__ __nv_bfloat16 g_wb[2048 * 4096];             // 16 MB: W planes [hi|lo]
__device__ float g_part[8 * B_ * OC_ * OF_];            // 16 MB: k-split partials

__device__ __forceinline__ float sqrt_ap(float v) {
    float r; asm("sqrt.approx.f32 %0, %1;" : "=f"(r) : "f"(v)); return r;
}
__device__ __forceinline__ float rcp_ap(float v) {
    float r; asm("rcp.approx.f32 %0, %1;" : "=f"(r) : "f"(v)); return r;
}
__device__ __forceinline__ uint32_t smem_u32(const void* p) {
    uint32_t a;
    asm("{ .reg .u64 t; cvta.to.shared.u64 t, %1; cvt.u32.u64 %0, t; }" : "=r"(a) : "l"(p));
    return a;
}
__device__ __forceinline__ void cp16(uint32_t s, const void* g) {
    asm volatile("cp.async.cg.shared.global [%0], [%1], 16;" :: "r"(s), "l"(g));
}
#define SWZ(o) ((o) ^ (((o) >> 3) & 0x70))

__device__ __forceinline__ void ldm4(uint32_t* r, uint32_t addr) {
    asm volatile("ldmatrix.sync.aligned.m8n8.x4.shared.b16 {%0,%1,%2,%3}, [%4];"
        : "=r"(r[0]), "=r"(r[1]), "=r"(r[2]), "=r"(r[3]) : "r"(addr));
}
__device__ __forceinline__ void mma16816(float* c, const uint32_t* a, uint32_t b0, uint32_t b1) {
    asm volatile("mma.sync.aligned.m16n8k16.row.col.f32.bf16.bf16.f32 "
        "{%0,%1,%2,%3}, {%4,%5,%6,%7}, {%8,%9}, {%0,%1,%2,%3};"
        : "+f"(c[0]), "+f"(c[1]), "+f"(c[2]), "+f"(c[3])
        : "r"(a[0]), "r"(a[1]), "r"(a[2]), "r"(a[3]), "r"(b0), "r"(b1));
}
__device__ __forceinline__ void split_bf16(float f, __nv_bfloat16& hb, __nv_bfloat16& lb) {
    hb = __float2bfloat16(f);
    lb = __float2bfloat16(f - __bfloat162float(hb));
}

// ---------------------------------------------------------------------------
// Kernel 1a: s2 logits. Grid 1024.
// ---------------------------------------------------------------------------
__global__ __launch_bounds__(256) void k1a_logits(
    const float* __restrict__ nb, const float* __restrict__ Wa2)
{
    __shared__ float ws2[256];
    const int b = blockIdx.x >> 2, quarter = blockIdx.x & 3;
    const int t = threadIdx.x;
    const int lane = t & 31, w = t >> 5;

    ws2[t] = Wa2[t] + Wa2[256 + t] + Wa2[512 + t] + Wa2[768 + t];
    __syncthreads();

    const float* nbb = nb + (size_t)b * 65536;
    #pragma unroll
    for (int j = 0; j < 2; j++) {
        const int n = quarter * 16 + w * 2 + j;
        const float4* np = (const float4*)(nbb + n * 1024);
        float acc = 0.f;
        #pragma unroll
        for (int it = 0; it < 8; it++) {
            float4 q = np[it * 32 + lane];
            int f = (it * 128 + lane * 4) & 255;
            acc += q.x * ws2[f] + q.y * ws2[f + 1] + q.z * ws2[f + 2] + q.w * ws2[f + 3];
        }
        #pragma unroll
        for (int o = 16; o > 0; o >>= 1) acc += __shfl_xor_sync(0xffffffffu, acc, o);
        if (lane == 0) g_s2[b * 64 + n] = acc;
    }
}

// ---------------------------------------------------------------------------
// Kernel 1b: s1 + softmax; write x directly as bf16 planes (channels 4..7).
// ---------------------------------------------------------------------------
__global__ __launch_bounds__(256) void k1b_softmax(
    const float* __restrict__ x, const float* __restrict__ Wa1)
{
    __shared__ float red[8];
    const int b = blockIdx.x;
    const int t = threadIdx.x;
    const int lane = t & 31, w = t >> 5;

    float w1 = Wa1[t] + Wa1[256 + t] + Wa1[512 + t] + Wa1[768 + t];

    float xs = 0.f;
    #pragma unroll
    for (int c = 0; c < 4; c++) {
        float xv = x[(b * 4 + c) * 256 + t];
        __nv_bfloat16 hb, lb;
        split_bf16(xv, hb, lb);
        const int k = (4 + c) * 256 + t;
        g_zb[b * 4096 + k]        = hb;
        g_zb[b * 4096 + 2048 + k] = lb;
        xs += xv;
    }
    float p = xs * w1;
    #pragma unroll
    for (int o = 16; o > 0; o >>= 1) p += __shfl_xor_sync(0xffffffffu, p, o);
    if (lane == 0) red[w] = p;
    __syncthreads();

    if (w == 0) {
        float s1v = red[lane & 7];
        #pragma unroll
        for (int o = 4; o > 0; o >>= 1) s1v += __shfl_xor_sync(0xffffffffu, s1v, o);
        float l0 = s1v * g_s2[b * 64 + lane];
        float l1 = s1v * g_s2[b * 64 + lane + 32];
        float m = fmaxf(l0, l1);
        #pragma unroll
        for (int o = 16; o > 0; o >>= 1) m = fmaxf(m, __shfl_xor_sync(0xffffffffu, m, o));
        float e0 = __expf(l0 - m), e1 = __expf(l1 - m);
        float s = e0 + e1;
        #pragma unroll
        for (int o = 16; o > 0; o >>= 1) s += __shfl_xor_sync(0xffffffffu, s, o);
        float inv = 1.f / s;
        g_w[b * 64 + lane]      = e0 * inv;
        g_w[b * 64 + lane + 32] = e1 * inv;
    }
}

// ---------------------------------------------------------------------------
// Kernel 2: v + adj + fused h (round-15 measured version, unchanged).
// ---------------------------------------------------------------------------
__global__ __launch_bounds__(256) void k2_adj(
    const float* __restrict__ x, const float* __restrict__ nb,
    float* __restrict__ adj)
{
    __shared__ float xs[256], vs[256], us[256], idn[256];
    __shared__ float wsm[64];
    __shared__ float pden[4 * 256];

    const int bc = blockIdx.x;
    const int b = bc >> 2, c = bc & 3;
    const int t = threadIdx.x;

    if (t < 64) wsm[t] = g_w[b * 64 + t];
    xs[t] = x[bc * 256 + t];
    __syncthreads();

    {
        const int fg = t & 63, ng = t >> 6;
        const float4* np4 = (const float4*)(nb + (size_t)b * 65536 + c * 256) + fg;
        float4 a4 = make_float4(0.f, 0.f, 0.f, 0.f);
        #pragma unroll 4
        for (int n = ng * 16; n < ng * 16 + 16; n++) {
            const float wn = wsm[n];
            const float4 q = np4[(size_t)n * 256];
            a4.x += wn * q.x; a4.y += wn * q.y; a4.z += wn * q.z; a4.w += wn * q.w;
        }
        *(float4*)&pden[ng * 256 + fg * 4] = a4;
    }
    __syncthreads();
    vs[t] = pden[t] + pden[256 + t] + pden[512 + t] + pden[768 + t];
    __syncthreads();

    const int r = t >> 6, cg = t & 63;
    const int i0 = r * 64;
    float xc[4], vc[4];
    #pragma unroll
    for (int j = 0; j < 4; j++) { xc[j] = xs[4 * cg + j]; vc[j] = vs[4 * cg + j]; }

    float d[4] = {0.f, 0.f, 0.f, 0.f};
    #pragma unroll 4
    for (int ii = 0; ii < 64; ii++) {
        const int i = i0 + ii;
        const float xi = xs[i], vi = vs[i];
        #pragma unroll
        for (int j = 0; j < 4; j++) {
            float tv = xi * vc[j] + xc[j] * vi;
            d[j] += sqrt_ap(fmaxf(fabsf(tv), 1e-8f));
        }
    }
    #pragma unroll
    for (int j = 0; j < 4; j++) pden[r * 256 + 4 * cg + j] = d[j];
    __syncthreads();

    {
        float den = pden[t] + pden[256 + t] + pden[512 + t] + pden[768 + t];
        float id = rcp_ap(den + 1e-7f);
        idn[t] = id;
        us[t] = xs[t] * id;
    }
    __syncthreads();

    float ic[4];
    #pragma unroll
    for (int j = 0; j < 4; j++) ic[j] = idn[4 * cg + j];
    float h[4] = {0.f, 0.f, 0.f, 0.f};
    float* ap = adj + (size_t)bc * 65536 + 4 * cg;

    #pragma unroll 4
    for (int ii = 0; ii < 64; ii++) {
        const int i = i0 + ii;
        const float xi = xs[i], vi = vs[i], usi = us[i];
        float4 o;
        #pragma unroll
        for (int j = 0; j < 4; j++) {
            float tv = xi * vc[j] + xc[j] * vi;
            float a = copysignf(sqrt_ap(fmaxf(fabsf(tv), 1e-8f)), tv);
            (&o.x)[j] = a * ic[j];
            h[j] = fmaf(a, usi, h[j]);
        }
        __stcs((float4*)(ap + (size_t)i * 256), o);
    }
    #pragma unroll
    for (int j = 0; j < 4; j++) pden[r * 256 + 4 * cg + j] = h[j];
    __syncthreads();

    float hs = pden[t] + pden[256 + t] + pden[512 + t] + pden[768 + t];
    __nv_bfloat16 hb, lb;
    split_bf16(hs, hb, lb);
    const int k = c * 256 + t;
    g_zb[b * 4096 + k]        = hb;
    g_zb[b * 4096 + 2048 + k] = lb;
}

// ---------------------------------------------------------------------------
// Kernel 3a: W fp32 -> bf16 planes [hi | lo].
// ---------------------------------------------------------------------------
__global__ __launch_bounds__(256) void k3a_convW(const float* __restrict__ src)
{
    const size_t idx = ((size_t)blockIdx.x * 256 + threadIdx.x) * 4;
    const int r = (int)(idx >> 11), k = (int)(idx & 2047);
    const float4 v = *(const float4*)(src + idx);
    ull hv = 0, lv = 0;
    #pragma unroll
    for (int j = 0; j < 4; j++) {
        __nv_bfloat16 hb, lb;
        split_bf16((&v.x)[j], hb, lb);
        hv |= (ull)__bfloat16_as_ushort(hb) << (16 * j);
        lv |= (ull)__bfloat16_as_ushort(lb) << (16 * j);
    }
    __nv_bfloat16* dst = g_wb + (size_t)r * 4096 + k;
    *(ull*)dst          = hv;
    *(ull*)(dst + 2048) = lv;
}

// ---------------------------------------------------------------------------
// Kernel 3: fused 3-product bf16 GEMM.
// acc = z_hi*W_hi + z_lo*W_hi + z_hi*W_lo accumulated in ONE pass: each chunk
// stages A-hi+A-lo and B-hi+B-lo packed [hi(64B)|lo(64B)] in one 128B SW128
// row. Staging drops 196MB -> 64MB (LDGSTS-issue was the binding pipe).
// CTA tile 128x128, 256 thr (8 warps, 2m x 4n, warp tile 64x32), chunk k=32,
// 3 stages x 32KB; grid (16 n, 2 m, 8 ksplit) = 256 CTAs.
// ---------------------------------------------------------------------------
#define NCH 8
#define STG_B 32768                            // A 16K + B 16K
#define K3_DSMEM (3 * STG_B + 1024)

__global__ __launch_bounds__(256, 2) void k3_mma(void)
{
    extern __shared__ char dsm[];
    const int t = threadIdx.x, wid = t >> 5, lane = t & 31;
    const int bn = blockIdx.x * 128, bm = blockIdx.y * 128;
    const int k0 = blockIdx.z * 256;
    const uint32_t base = (smem_u32(dsm) + 1023) & ~1023u;

    const int wm = (wid & 1) * 64, wn = (wid >> 1) * 32;

    // loader: thread (row, half): 4 x cp16 each for A and B
    const int lrow = t & 127, lhalf = t >> 7;      // half: 0 = hi, 1 = lo
    uint32_t swo[4];
    #pragma unroll
    for (int j = 0; j < 4; j++) swo[j] = SWZ((uint32_t)(lrow * 128 + lhalf * 64 + j * 16));
    const __nv_bfloat16* gA = g_zb + (size_t)(bm + lrow) * 4096 + lhalf * 2048 + k0;
    const __nv_bfloat16* gB = g_wb + (size_t)(bn + lrow) * 4096 + lhalf * 2048 + k0;

    #define LOAD(ch) do { \
        const uint32_t sA_ = base + ((ch) % 3) * STG_B; \
        const uint32_t sB_ = sA_ + 16384; \
        const __nv_bfloat16* pa_ = gA + (ch) * 32; \
        const __nv_bfloat16* pb_ = gB + (ch) * 32; \
        _Pragma("unroll") \
        for (int j = 0; j < 4; j++) { cp16(sA_ + swo[j], pa_ + j * 8); cp16(sB_ + swo[j], pb_ + j * 8); } \
        asm volatile("cp.async.commit_group;" ::: "memory"); \
    } while (0)

    // ldmatrix components (verified round-11 formulas + plane*64 byte offset)
    const uint32_t a_rb = (wm + (lane & 15)) * 128 + (lane >> 4) * 16;           // + mf*16*128 + ks*32 + plane*64
    const uint32_t b_rb = (wn + (lane & 7) + ((lane >> 4) << 3)) * 128 + ((lane >> 3) & 1) * 16;  // + bg*16*128 + ks*32 + plane*64

    float acc[4][4][4];
    #pragma unroll
    for (int mf = 0; mf < 4; mf++)
        #pragma unroll
        for (int nf = 0; nf < 4; nf++)
            #pragma unroll
            for (int e = 0; e < 4; e++) acc[mf][nf][e] = 0.f;

    LOAD(0);
    LOAD(1);

    for (int ch = 0; ch < NCH; ch++) {
        if (ch < NCH - 1) asm volatile("cp.async.wait_group 1;" ::: "memory");
        else              asm volatile("cp.async.wait_group 0;" ::: "memory");
        __syncthreads();
        if (ch + 2 < NCH) LOAD(ch + 2);

        const uint32_t sA = base + (ch % 3) * STG_B;
        const uint32_t sB = sA + 16384;
        #pragma unroll
        for (int ks = 0; ks < 2; ks++) {
            uint32_t ah[4][4], al[4][4], bh[2][4], bl[2][4];
            #pragma unroll
            for (int mf = 0; mf < 4; mf++) {
                ldm4(ah[mf], sA + SWZ(a_rb + mf * 16 * 128 + ks * 32));
                ldm4(al[mf], sA + SWZ(a_rb + mf * 16 * 128 + ks * 32 + 64));
            }
            #pragma unroll
            for (int bg = 0; bg < 2; bg++) {
                ldm4(bh[bg], sB + SWZ(b_rb + bg * 16 * 128 + ks * 32));
                ldm4(bl[bg], sB + SWZ(b_rb + bg * 16 * 128 + ks * 32 + 64));
            }
            #pragma unroll
            for (int mf = 0; mf < 4; mf++) {
                // hi*hi
                mma16816(acc[mf][0], ah[mf], bh[0][0], bh[0][1]);
                mma16816(acc[mf][1], ah[mf], bh[0][2], bh[0][3]);
                mma16816(acc[mf][2], ah[mf], bh[1][0], bh[1][1]);
                mma16816(acc[mf][3], ah[mf], bh[1][2], bh[1][3]);
                // lo*hi
                mma16816(acc[mf][0], al[mf], bh[0][0], bh[0][1]);
                mma16816(acc[mf][1], al[mf], bh[0][2], bh[0][3]);
                mma16816(acc[mf][2], al[mf], bh[1][0], bh[1][1]);
                mma16816(acc[mf][3], al[mf], bh[1][2], bh[1][3]);
                // hi*lo
                mma16816(acc[mf][0], ah[mf], bl[0][0], bl[0][1]);
                mma16816(acc[mf][1], ah[mf], bl[0][2], bl[0][3]);
                mma16816(acc[mf][2], ah[mf], bl[1][0], bl[1][1]);
                mma16816(acc[mf][3], ah[mf], bl[1][2], bl[1][3]);
            }
        }
    }
    #undef LOAD

    float* pp = g_part + (size_t)blockIdx.z * 524288;
    const int gid = lane >> 2, cpo = 2 * (lane & 3);
    #pragma unroll
    for (int mf = 0; mf < 4; mf++) {
        const int row0 = bm + wm + mf * 16 + gid;
        #pragma unroll
        for (int nf = 0; nf < 4; nf++) {
            const int col = bn + wn + nf * 8 + cpo;
            *(float2*)(pp + (size_t)row0 * 2048 + col)       = make_float2(acc[mf][nf][0], acc[mf][nf][1]);
            *(float2*)(pp + (size_t)(row0 + 8) * 2048 + col) = make_float2(acc[mf][nf][2], acc[mf][nf][3]);
        }
    }
}

// ---------------------------------------------------------------------------
// Kernel 4: sum the 8 k-split partials into out.
// ---------------------------------------------------------------------------
__global__ __launch_bounds__(256) void k4_reduce(float* __restrict__ out)
{
    const int i = (blockIdx.x * 256 + threadIdx.x) * 4;
    float4 o = *(const float4*)(g_part + i);
    #pragma unroll
    for (int s = 1; s < 8; s++) {
        const float4 p = *(const float4*)(g_part + (size_t)s * 524288 + i);
        o.x += p.x; o.y += p.y; o.z += p.z; o.w += p.w;
    }
    *(float4*)(out + i) = o;
}

// ---------------------------------------------------------------------------
// Launch: output layout = concat(out (B*OC*OF), adj (B*C*F*F)) in fp32.
// convW overlaps k2 on a side stream; rest serial.
// ---------------------------------------------------------------------------
extern "C" void kernel_launch(void* const* d_in, const int* in_sizes, int n_in,
                              void* d_out, int out_size)
{
    const float* x   = (const float*)d_in[0];
    const float* nb  = (const float*)d_in[1];
    const float* Wa1 = (const float*)d_in[2];
    const float* Wa2 = (const float*)d_in[3];
    const float* Wc  = (const float*)d_in[4];
    float* out = (float*)d_out;
    float* adj = out + (size_t)B_ * OC_ * OF_;

    static cudaStream_t s1 = 0;
    static cudaEvent_t evFork = 0, evJoin = 0;
    static int init_done = 0;
    if (!init_done) {
        cudaFuncSetAttribute(k3_mma, cudaFuncAttributeMaxDynamicSharedMemorySize, K3_DSMEM);
        if (cudaStreamCreateWithFlags(&s1, cudaStreamNonBlocking) != cudaSuccess) s1 = 0;
        if (cudaEventCreateWithFlags(&evFork, cudaEventDisableTiming) != cudaSuccess) evFork = 0;
        if (cudaEventCreateWithFlags(&evJoin, cudaEventDisableTiming) != cudaSuccess) evJoin = 0;
        if (!evFork || !evJoin) s1 = 0;   // serial fallback
        init_done = 1;
    }

    k1a_logits<<<B_ * 4, 256>>>(nb, Wa2);
    k1b_softmax<<<B_, 256>>>(x, Wa1);

    if (s1) {
        cudaEventRecord(evFork, 0);
        cudaStreamWaitEvent(s1, evFork, 0);
    }
    k3a_convW<<<4096, 256, 0, s1>>>(Wc);       // side: overlaps k2
    if (s1) cudaEventRecord(evJoin, s1);

    k2_adj<<<B_ * C_, 256>>>(x, nb, adj);
    if (s1) cudaStreamWaitEvent(0, evJoin, 0);
    k3_mma<<<dim3(16, 2, 8), 256, K3_DSMEM>>>();
    k4_reduce<<<512, 256>>>(out);
}